// round 1
// baseline (speedup 1.0000x reference)
#include <cuda_runtime.h>

// ---------------- problem constants ----------------
#define BLn    8192      // B * L
#define LSEQ   4096
#define DIMI   2048
#define DINn   8512      // 2*HID + 2*G*N + H
#define HIDC   4096
#define CONVD  4352      // HID + 2*G*N
#define NHh    64        // heads
#define PD     64        // head dim
#define NS     128       // state dim
#define QC     128       // chunk len
#define NCT    64        // total chunks = B * (L/Q)

// ---------------- scratch (device globals; allocation-free rule) ----------------
__device__ float g_zx[(size_t)BLn * DINn];        // in-proj output (z | xBC | dt_raw)
__device__ float g_conv[(size_t)BLn * CONVD];     // conv+silu output (xs | B | C)
__device__ float g_dt[BLn * NHh];                 // softplus(dt_raw + bias)
__device__ float g_cum[BLn * NHh];                // per-chunk cumsum of dt*A
__device__ float g_CB[NCT * QC * QC];             // per-chunk C·B^T gram
__device__ float g_states[(size_t)NCT * NHh * PD * NS];  // chunk states, then Sprev in-place
__device__ float g_y[(size_t)BLn * HIDC];         // y, then yn in-place

__device__ __forceinline__ void fma4(float4& a, float s, const float4 v) {
    a.x += s * v.x; a.y += s * v.y; a.z += s * v.z; a.w += s * v.w;
}

// ---------------- generic C = A(MxK) * B(NxK)^T, fp32 SIMT tiled ----------------
__global__ void __launch_bounds__(256) gemm_nt_kernel(
    const float* __restrict__ A, const float* __restrict__ B, float* __restrict__ C,
    int M, int N, int K)
{
    __shared__ float As[16][128];
    __shared__ float Bs[16][128];
    const int tid = threadIdx.x;
    const int tx = tid & 15;
    const int ty = tid >> 4;
    const int cRow = blockIdx.y * 128;
    const int cCol = blockIdx.x * 128;

    const int la  = tid * 2;
    const int r0  = la >> 2;           // shared row (0..127)
    const int k0o = (la & 3) * 4;      // 0 or 8
    const int k1o = ((la + 1) & 3) * 4;// 4 or 12

    float acc[8][8];
    #pragma unroll
    for (int i = 0; i < 8; i++)
        #pragma unroll
        for (int j = 0; j < 8; j++) acc[i][j] = 0.f;

    const bool bok = (cCol + r0) < N;

    for (int kb = 0; kb < K; kb += 16) {
        float4 av0 = *reinterpret_cast<const float4*>(A + (size_t)(cRow + r0) * K + kb + k0o);
        float4 av1 = *reinterpret_cast<const float4*>(A + (size_t)(cRow + r0) * K + kb + k1o);
        float4 bv0 = make_float4(0.f, 0.f, 0.f, 0.f), bv1 = bv0;
        if (bok) {
            bv0 = *reinterpret_cast<const float4*>(B + (size_t)(cCol + r0) * K + kb + k0o);
            bv1 = *reinterpret_cast<const float4*>(B + (size_t)(cCol + r0) * K + kb + k1o);
        }
        __syncthreads();
        As[k0o + 0][r0] = av0.x; As[k0o + 1][r0] = av0.y; As[k0o + 2][r0] = av0.z; As[k0o + 3][r0] = av0.w;
        As[k1o + 0][r0] = av1.x; As[k1o + 1][r0] = av1.y; As[k1o + 2][r0] = av1.z; As[k1o + 3][r0] = av1.w;
        Bs[k0o + 0][r0] = bv0.x; Bs[k0o + 1][r0] = bv0.y; Bs[k0o + 2][r0] = bv0.z; Bs[k0o + 3][r0] = bv0.w;
        Bs[k1o + 0][r0] = bv1.x; Bs[k1o + 1][r0] = bv1.y; Bs[k1o + 2][r0] = bv1.z; Bs[k1o + 3][r0] = bv1.w;
        __syncthreads();
        #pragma unroll
        for (int kk = 0; kk < 16; kk++) {
            float4 a0 = *(const float4*)&As[kk][ty * 8];
            float4 a1 = *(const float4*)&As[kk][ty * 8 + 4];
            float4 b0 = *(const float4*)&Bs[kk][tx * 8];
            float4 b1 = *(const float4*)&Bs[kk][tx * 8 + 4];
            float a[8] = {a0.x, a0.y, a0.z, a0.w, a1.x, a1.y, a1.z, a1.w};
            float b[8] = {b0.x, b0.y, b0.z, b0.w, b1.x, b1.y, b1.z, b1.w};
            #pragma unroll
            for (int i = 0; i < 8; i++)
                #pragma unroll
                for (int j = 0; j < 8; j++) acc[i][j] += a[i] * b[j];
        }
    }
    #pragma unroll
    for (int i = 0; i < 8; i++) {
        int r = cRow + ty * 8 + i;
        #pragma unroll
        for (int j0 = 0; j0 < 8; j0 += 4) {
            int c = cCol + tx * 8 + j0;
            if (c < N)  // N always multiple of 4
                *reinterpret_cast<float4*>(C + (size_t)r * N + c) =
                    make_float4(acc[i][j0], acc[i][j0 + 1], acc[i][j0 + 2], acc[i][j0 + 3]);
        }
    }
}

// ---------------- causal depthwise conv (K=4) + SiLU ----------------
__global__ void __launch_bounds__(256) conv_silu_kernel(const float* __restrict__ w) {
    size_t idx = (size_t)blockIdx.x * 256 + threadIdx.x;   // over BL*CONVD
    int c = (int)(idx % CONVD);
    int bl = (int)(idx / CONVD);
    int l = bl & (LSEQ - 1);
    float acc = 0.f;
    #pragma unroll
    for (int k = 0; k < 4; k++) {
        int lo = l - 3 + k;
        if (lo >= 0)
            acc += g_zx[(size_t)(bl - 3 + k) * DINn + HIDC + c] * w[c * 4 + k];
    }
    float s = 1.f / (1.f + expf(-acc));
    g_conv[(size_t)bl * CONVD + c] = acc * s;
}

// ---------------- dt = softplus(dt_raw + bias) ----------------
__global__ void __launch_bounds__(256) dt_kernel(const float* __restrict__ dt_bias) {
    int idx = blockIdx.x * 256 + threadIdx.x;    // over BL*NH
    int h = idx & 63;
    int bl = idx >> 6;
    float v = g_zx[(size_t)bl * DINn + (HIDC + CONVD) + h] + dt_bias[h];
    float d = (v > 20.f) ? v : log1pf(expf(v));
    g_dt[idx] = d;
}

// ---------------- per-chunk cumsum of dt*A ----------------
__global__ void cum_kernel(const float* __restrict__ A_log) {
    int ch = blockIdx.x;       // 0..63
    int h = threadIdx.x;       // 0..63
    float A = -expf(A_log[h]);
    float run = 0.f;
    for (int q = 0; q < QC; q++) {
        int r = (ch * QC + q) * NHh + h;
        run += g_dt[r] * A;
        g_cum[r] = run;
    }
}

// ---------------- per-chunk CB[i][j] = sum_n C[i,n]*B[j,n] ----------------
__global__ void __launch_bounds__(256) cb_kernel() {
    extern __shared__ float sh[];
    float* Bsh = sh;             // 128 x 129
    float* Csh = sh + 16512;     // 128 x 129
    int ch = blockIdx.x;
    int tid = threadIdx.x;
    for (int idx = tid; idx < 16384; idx += 256) {
        int i = idx >> 7, n = idx & 127;
        size_t row = (size_t)(ch * QC + i) * CONVD;
        Bsh[i * 129 + n] = g_conv[row + HIDC + n];
        Csh[i * 129 + n] = g_conv[row + HIDC + NS + n];
    }
    __syncthreads();
    int tx = tid & 15, ty = tid >> 4;
    float acc[8][8];
    #pragma unroll
    for (int i = 0; i < 8; i++)
        #pragma unroll
        for (int j = 0; j < 8; j++) acc[i][j] = 0.f;
    for (int n = 0; n < NS; n++) {
        float a[8], b[8];
        #pragma unroll
        for (int u = 0; u < 8; u++) a[u] = Csh[(ty * 8 + u) * 129 + n];
        #pragma unroll
        for (int u = 0; u < 8; u++) b[u] = Bsh[(tx * 8 + u) * 129 + n];
        #pragma unroll
        for (int i = 0; i < 8; i++)
            #pragma unroll
            for (int j = 0; j < 8; j++) acc[i][j] += a[i] * b[j];
    }
    #pragma unroll
    for (int i = 0; i < 8; i++)
        #pragma unroll
        for (int j0 = 0; j0 < 8; j0 += 4)
            *reinterpret_cast<float4*>(&g_CB[ch * 16384 + (ty * 8 + i) * 128 + tx * 8 + j0]) =
                make_float4(acc[i][j0], acc[i][j0 + 1], acc[i][j0 + 2], acc[i][j0 + 3]);
}

// ---------------- chunk states: states[h,p,n] = sum_q wdec[q]*xs[q,p]*B[q,n] ----------------
__global__ void __launch_bounds__(256) states_kernel() {
    __shared__ float Bs[32 * 128];
    __shared__ float xss[32 * 64];
    __shared__ float wdec[128];
    __shared__ float cl;
    const int h = blockIdx.x, ch = blockIdx.y;
    const int tid = threadIdx.x;
    if (tid == 0) cl = g_cum[(ch * QC + QC - 1) * NHh + h];
    __syncthreads();
    if (tid < 128) {
        int r = (ch * QC + tid) * NHh + h;
        wdec[tid] = __expf(cl - g_cum[r]) * g_dt[r];
    }
    const int p = tid >> 2, ng = tid & 3;
    float4 acc4[8];
    #pragma unroll
    for (int u = 0; u < 8; u++) acc4[u] = make_float4(0.f, 0.f, 0.f, 0.f);

    for (int qt = 0; qt < 4; qt++) {
        __syncthreads();
        for (int idx = tid; idx < 4096; idx += 256) {
            int qq = idx >> 7, n = idx & 127;
            Bs[idx] = g_conv[(size_t)(ch * QC + qt * 32 + qq) * CONVD + HIDC + n];
        }
        for (int idx = tid; idx < 2048; idx += 256) {
            int qq = idx >> 6, pp = idx & 63;
            xss[idx] = g_conv[(size_t)(ch * QC + qt * 32 + qq) * CONVD + h * PD + pp];
        }
        __syncthreads();
        #pragma unroll 4
        for (int qq = 0; qq < 32; qq++) {
            float coef = wdec[qt * 32 + qq] * xss[qq * 64 + p];
            const float4* bp = (const float4*)&Bs[qq * 128 + ng * 32];
            #pragma unroll
            for (int u = 0; u < 8; u++) fma4(acc4[u], coef, bp[u]);
        }
    }
    size_t base = ((size_t)ch * NHh + h) * (PD * NS) + (size_t)p * NS + ng * 32;
    #pragma unroll
    for (int u = 0; u < 8; u++)
        *reinterpret_cast<float4*>(&g_states[base + u * 4]) = acc4[u];
}

// ---------------- sequential inter-chunk scan (in-place: states -> Sprev) ----------------
__global__ void __launch_bounds__(256) scan_kernel() {
    const int h = blockIdx.x, b = blockIdx.y;
    const int t = threadIdx.x;
    float S[32];
    #pragma unroll
    for (int i = 0; i < 32; i++) S[i] = 0.f;
    for (int c = 0; c < 32; c++) {
        int ch = b * 32 + c;
        float dec = __expf(g_cum[(ch * QC + QC - 1) * NHh + h]);
        size_t base = ((size_t)ch * NHh + h) * (PD * NS);
        #pragma unroll
        for (int i = 0; i < 32; i++) {
            size_t id = base + (size_t)i * 256 + t;
            float st = g_states[id];
            g_states[id] = S[i];               // Sprev (state before this chunk)
            S[i] = S[i] * dec + st;
        }
    }
}

// ---------------- Yd + Yoff + D*xs -> y ----------------
__global__ void __launch_bounds__(256) ydyoff_kernel(const float* __restrict__ Dvec) {
    extern __shared__ float sh[];
    float* CBs   = sh;                 // 128 x 129
    float* Cs    = sh + 16512;         // 128 x 129
    float* SpT   = sh + 33024;         // [n][p] 128 x 64
    float* xss   = sh + 41216;         // [j][p] 128 x 64
    float* cum_s = sh + 49408;         // 128
    float* dt_s  = sh + 49536;         // 128
    const int h = blockIdx.x, ch = blockIdx.y, tid = threadIdx.x;

    for (int idx = tid; idx < 16384; idx += 256) {
        int i = idx >> 7, j = idx & 127;
        CBs[i * 129 + j] = g_CB[ch * 16384 + idx];
        Cs[i * 129 + j]  = g_conv[(size_t)(ch * QC + i) * CONVD + HIDC + NS + j];
    }
    for (int idx = tid; idx < 8192; idx += 256) {
        int p = idx >> 7, n = idx & 127;
        SpT[n * 64 + p] = g_states[((size_t)ch * NHh + h) * (PD * NS) + idx];
        xss[idx] = g_conv[(size_t)(ch * QC + (idx >> 6)) * CONVD + h * PD + (idx & 63)];
    }
    if (tid < 128) {
        int r = (ch * QC + tid) * NHh + h;
        cum_s[tid] = g_cum[r];
        dt_s[tid]  = g_dt[r];
    }
    __syncthreads();

    const int i = tid >> 1, ph = tid & 1;
    float4 aD[8], aO[8];
    #pragma unroll
    for (int u = 0; u < 8; u++) { aD[u] = make_float4(0.f,0.f,0.f,0.f); aO[u] = make_float4(0.f,0.f,0.f,0.f); }
    const float ci = cum_s[i];

    // intra-chunk (lower-triangular) attention
    for (int j = 0; j <= i; j++) {
        float m = CBs[i * 129 + j] * __expf(ci - cum_s[j]) * dt_s[j];
        const float4* xr = (const float4*)&xss[j * 64 + ph * 32];
        #pragma unroll
        for (int u = 0; u < 8; u++) fma4(aD[u], m, xr[u]);
    }
    // carried-state contribution
    #pragma unroll 4
    for (int n = 0; n < NS; n++) {
        float cv = Cs[i * 129 + n];
        const float4* sr = (const float4*)&SpT[n * 64 + ph * 32];
        #pragma unroll
        for (int u = 0; u < 8; u++) fma4(aO[u], cv, sr[u]);
    }
    const float ei = __expf(ci);
    const float Dh = Dvec[h];
    const float* xi = &xss[i * 64 + ph * 32];
    float* yo = &g_y[(size_t)(ch * QC + i) * HIDC + h * PD + ph * 32];
    #pragma unroll
    for (int u = 0; u < 8; u++) {
        float4 d = aD[u], o = aO[u];
        float4 r;
        r.x = d.x + ei * o.x + Dh * xi[u * 4 + 0];
        r.y = d.y + ei * o.y + Dh * xi[u * 4 + 1];
        r.z = d.z + ei * o.z + Dh * xi[u * 4 + 2];
        r.w = d.w + ei * o.w + Dh * xi[u * 4 + 3];
        *reinterpret_cast<float4*>(&yo[u * 4]) = r;
    }
}

// ---------------- gate with silu(z) + RMSNorm (in-place on g_y) ----------------
__global__ void __launch_bounds__(256) gating_kernel(const float* __restrict__ norm_w) {
    __shared__ float red[256];
    const int bl = blockIdx.x, tid = threadIdx.x;
    float vals[16];
    float ss = 0.f;
    #pragma unroll
    for (int it = 0; it < 16; it++) {
        int idx = it * 256 + tid;
        float yv = g_y[(size_t)bl * HIDC + idx];
        float z  = g_zx[(size_t)bl * DINn + idx];
        float yz = yv * (z / (1.f + expf(-z)));
        vals[it] = yz;
        ss += yz * yz;
    }
    red[tid] = ss;
    __syncthreads();
    for (int s = 128; s > 0; s >>= 1) {
        if (tid < s) red[tid] += red[tid + s];
        __syncthreads();
    }
    float sc = rsqrtf(red[0] / (float)HIDC + 1e-5f);
    #pragma unroll
    for (int it = 0; it < 16; it++) {
        int idx = it * 256 + tid;
        g_y[(size_t)bl * HIDC + idx] = vals[it] * sc * norm_w[idx];
    }
}

// ---------------- launch ----------------
extern "C" void kernel_launch(void* const* d_in, const int* in_sizes, int n_in,
                              void* d_out, int out_size) {
    const float* x       = (const float*)d_in[0];
    const float* W_in    = (const float*)d_in[1];
    const float* conv_w  = (const float*)d_in[2];
    const float* dt_bias = (const float*)d_in[3];
    const float* A_log   = (const float*)d_in[4];
    const float* Dv      = (const float*)d_in[5];
    const float* norm_w  = (const float*)d_in[6];
    const float* W_out   = (const float*)d_in[7];
    float* out = (float*)d_out;

    float *zx_p, *y_p;
    cudaGetSymbolAddress((void**)&zx_p, g_zx);
    cudaGetSymbolAddress((void**)&y_p, g_y);

    cudaFuncSetAttribute(cb_kernel, cudaFuncAttributeMaxDynamicSharedMemorySize, 132096);
    cudaFuncSetAttribute(ydyoff_kernel, cudaFuncAttributeMaxDynamicSharedMemorySize, 198656);

    // 1) in-proj GEMM: (8192 x 2048) * (8512 x 2048)^T
    gemm_nt_kernel<<<dim3(67, 64), 256>>>(x, W_in, zx_p, BLn, DINn, DIMI);
    // 2) causal conv + silu
    conv_silu_kernel<<<(BLn * CONVD) / 256, 256>>>(conv_w);
    // 3) dt softplus
    dt_kernel<<<(BLn * NHh) / 256, 256>>>(dt_bias);
    // 4) per-chunk cumsum of dt*A
    cum_kernel<<<NCT, NHh>>>(A_log);
    // 5) per-chunk CB gram
    cb_kernel<<<NCT, 256, 132096>>>();
    // 6) chunk states
    states_kernel<<<dim3(NHh, NCT), 256>>>();
    // 7) inter-chunk scan -> Sprev
    scan_kernel<<<dim3(NHh, 2), 256>>>();
    // 8) Yd + Yoff + D*xs
    ydyoff_kernel<<<dim3(NHh, NCT), 256, 198656>>>(Dv);
    // 9) gate + rmsnorm
    gating_kernel<<<BLn, 256>>>(norm_w);
    // 10) out-proj GEMM: (8192 x 4096) * (2048 x 4096)^T
    gemm_nt_kernel<<<dim3(16, 64), 256>>>(y_p, W_out, out, BLn, DIMI, HIDC);
}

// round 3
// speedup vs baseline: 1.7673x; 1.7673x over previous
#include <cuda_runtime.h>
#include <cstdint>

// ---------------- problem constants ----------------
#define BLn    8192      // B * L
#define LSEQ   4096
#define DIMI   2048
#define DINn   8512      // 2*HID + 2*G*N + H
#define HIDC   4096
#define CONVD  4352      // HID + 2*G*N
#define NHh    64        // heads
#define PD     64        // head dim
#define NS     128       // state dim
#define QC     128       // chunk len
#define NCT    64        // total chunks = B * (L/Q)

// ---------------- scratch (device globals; allocation-free rule) ----------------
__device__ float g_zx[(size_t)BLn * DINn];        // in-proj output (z | xBC | dt_raw)
__device__ float g_conv[(size_t)BLn * CONVD];     // conv+silu output (xs | B | C)
__device__ float g_dt[BLn * NHh];                 // softplus(dt_raw + bias)
__device__ float g_cum[BLn * NHh];                // per-chunk cumsum of dt*A
__device__ float g_CB[NCT * QC * QC];             // per-chunk C.B^T gram
__device__ float g_states[(size_t)NCT * NHh * PD * NS];  // chunk states, then Sprev in-place
__device__ float g_y[(size_t)BLn * HIDC];         // y, then yn in-place

__device__ __forceinline__ void fma4(float4& a, float s, const float4 v) {
    a.x += s * v.x; a.y += s * v.y; a.z += s * v.z; a.w += s * v.w;
}

// =======================================================================
//  tf32 mma.sync GEMM:  C[M,N] = A[M,K] * B[N,K]^T   (K-major fp32 in/out)
//  CTA tile 256x128, 8 warps (4x2), warp tile 64x64, K-step 16, dbl-buffer
// =======================================================================

__device__ __forceinline__ uint32_t f2tf32(float f) {
    uint32_t r;
    asm("cvt.rna.tf32.f32 %0, %1;" : "=r"(r) : "f"(f));
    return r;
}

__device__ __forceinline__ void mma_tf32(float* d, const uint32_t* a, const uint32_t* b) {
    asm volatile(
        "mma.sync.aligned.m16n8k8.row.col.f32.tf32.tf32.f32 "
        "{%0,%1,%2,%3}, {%4,%5,%6,%7}, {%8,%9}, {%0,%1,%2,%3};"
        : "+f"(d[0]), "+f"(d[1]), "+f"(d[2]), "+f"(d[3])
        : "r"(a[0]), "r"(a[1]), "r"(a[2]), "r"(a[3]), "r"(b[0]), "r"(b[1]));
}

#define ASTR  20                         // padded row stride (u32) — conflict-free
#define SSTR  ((256 + 128) * ASTR)       // per-stage stride (u32)
#define GTC_SMEM (2 * SSTR * 4)          // 61440 bytes

__global__ void __launch_bounds__(256) gemm_tc_kernel(
    const float* __restrict__ A, const float* __restrict__ B, float* __restrict__ C,
    int M, int Nn, int K)
{
    extern __shared__ uint32_t sm[];
    const int tid  = threadIdx.x;
    const int wid  = tid >> 5, lane = tid & 31;
    const int gID  = lane >> 2, tig = lane & 3;
    const int wM   = (wid >> 1) * 64;    // warp M offset in CTA tile
    const int wN   = (wid & 1) * 64;     // warp N offset
    const int cRow = blockIdx.y * 256;
    const int cCol = blockIdx.x * 128;
    const int KT   = K >> 4;

    float acc[4][8][4];
    #pragma unroll
    for (int mi = 0; mi < 4; mi++)
        #pragma unroll
        for (int ni = 0; ni < 8; ni++)
            #pragma unroll
            for (int u = 0; u < 4; u++) acc[mi][ni][u] = 0.f;

    // per-thread gmem load coords (A: 1024 float4, B: 512 float4)
    // A: i = v*256+tid -> row i>>2, col4 (i&3)*4 ; B: v 0..1 same mapping
    // ---- prologue: tile 0 straight to smem stage 0 ----
    {
        uint32_t* As = sm;
        uint32_t* Bs = sm + 256 * ASTR;
        #pragma unroll
        for (int v = 0; v < 4; v++) {
            int i = v * 256 + tid, row = i >> 2, c4 = (i & 3) * 4;
            float4 av = *reinterpret_cast<const float4*>(A + (size_t)(cRow + row) * K + c4);
            uint32_t* p = As + row * ASTR + c4;
            p[0] = f2tf32(av.x); p[1] = f2tf32(av.y); p[2] = f2tf32(av.z); p[3] = f2tf32(av.w);
        }
        #pragma unroll
        for (int v = 0; v < 2; v++) {
            int i = v * 256 + tid, row = i >> 2, c4 = (i & 3) * 4;
            float4 bv = make_float4(0.f, 0.f, 0.f, 0.f);
            if (cCol + row < Nn)
                bv = *reinterpret_cast<const float4*>(B + (size_t)(cCol + row) * K + c4);
            uint32_t* p = Bs + row * ASTR + c4;
            p[0] = f2tf32(bv.x); p[1] = f2tf32(bv.y); p[2] = f2tf32(bv.z); p[3] = f2tf32(bv.w);
        }
    }
    __syncthreads();

    for (int kt = 0; kt < KT; kt++) {
        const int b = kt & 1;
        const uint32_t* As = sm + b * SSTR;
        const uint32_t* Bs = As + 256 * ASTR;

        // issue next tile's gmem loads early
        float4 ra[4], rb[2];
        const bool more = (kt + 1 < KT);
        if (more) {
            const int kb = (kt + 1) << 4;
            #pragma unroll
            for (int v = 0; v < 4; v++) {
                int i = v * 256 + tid, row = i >> 2, c4 = (i & 3) * 4;
                ra[v] = *reinterpret_cast<const float4*>(A + (size_t)(cRow + row) * K + kb + c4);
            }
            #pragma unroll
            for (int v = 0; v < 2; v++) {
                int i = v * 256 + tid, row = i >> 2, c4 = (i & 3) * 4;
                rb[v] = make_float4(0.f, 0.f, 0.f, 0.f);
                if (cCol + row < Nn)
                    rb[v] = *reinterpret_cast<const float4*>(B + (size_t)(cCol + row) * K + kb + c4);
            }
        }

        // compute on stage b
        #pragma unroll
        for (int kk = 0; kk < 2; kk++) {
            uint32_t af[4][4], bf[8][2];
            const int col = kk * 8 + tig;
            #pragma unroll
            for (int mi = 0; mi < 4; mi++) {
                const int r = wM + mi * 16 + gID;
                af[mi][0] = As[r * ASTR + col];
                af[mi][1] = As[(r + 8) * ASTR + col];
                af[mi][2] = As[r * ASTR + col + 4];
                af[mi][3] = As[(r + 8) * ASTR + col + 4];
            }
            #pragma unroll
            for (int ni = 0; ni < 8; ni++) {
                const int r = wN + ni * 8 + gID;
                bf[ni][0] = Bs[r * ASTR + col];
                bf[ni][1] = Bs[r * ASTR + col + 4];
            }
            #pragma unroll
            for (int mi = 0; mi < 4; mi++)
                #pragma unroll
                for (int ni = 0; ni < 8; ni++)
                    mma_tf32(acc[mi][ni], af[mi], bf[ni]);
        }

        // store next tile into the other stage
        if (more) {
            uint32_t* As2 = sm + (b ^ 1) * SSTR;
            uint32_t* Bs2 = As2 + 256 * ASTR;
            #pragma unroll
            for (int v = 0; v < 4; v++) {
                int i = v * 256 + tid, row = i >> 2, c4 = (i & 3) * 4;
                uint32_t* p = As2 + row * ASTR + c4;
                p[0] = f2tf32(ra[v].x); p[1] = f2tf32(ra[v].y);
                p[2] = f2tf32(ra[v].z); p[3] = f2tf32(ra[v].w);
            }
            #pragma unroll
            for (int v = 0; v < 2; v++) {
                int i = v * 256 + tid, row = i >> 2, c4 = (i & 3) * 4;
                uint32_t* p = Bs2 + row * ASTR + c4;
                p[0] = f2tf32(rb[v].x); p[1] = f2tf32(rb[v].y);
                p[2] = f2tf32(rb[v].z); p[3] = f2tf32(rb[v].w);
            }
        }
        __syncthreads();
    }

    // epilogue: direct gmem stores (float2 per c0/c1 pair)
    #pragma unroll
    for (int mi = 0; mi < 4; mi++) {
        const int r0 = cRow + wM + mi * 16 + gID;
        #pragma unroll
        for (int ni = 0; ni < 8; ni++) {
            const int c = cCol + wN + ni * 8 + tig * 2;
            if (c < Nn) {
                *reinterpret_cast<float2*>(C + (size_t)r0 * Nn + c) =
                    make_float2(acc[mi][ni][0], acc[mi][ni][1]);
                *reinterpret_cast<float2*>(C + (size_t)(r0 + 8) * Nn + c) =
                    make_float2(acc[mi][ni][2], acc[mi][ni][3]);
            }
        }
    }
}

// ---------------- causal depthwise conv (K=4) + SiLU ----------------
__global__ void __launch_bounds__(256) conv_silu_kernel(const float* __restrict__ w) {
    size_t idx = (size_t)blockIdx.x * 256 + threadIdx.x;   // over BL*CONVD
    int c = (int)(idx % CONVD);
    int bl = (int)(idx / CONVD);
    int l = bl & (LSEQ - 1);
    float acc = 0.f;
    #pragma unroll
    for (int k = 0; k < 4; k++) {
        int lo = l - 3 + k;
        if (lo >= 0)
            acc += g_zx[(size_t)(bl - 3 + k) * DINn + HIDC + c] * w[c * 4 + k];
    }
    float s = 1.f / (1.f + expf(-acc));
    g_conv[(size_t)bl * CONVD + c] = acc * s;
}

// ---------------- dt = softplus(dt_raw + bias) ----------------
__global__ void __launch_bounds__(256) dt_kernel(const float* __restrict__ dt_bias) {
    int idx = blockIdx.x * 256 + threadIdx.x;    // over BL*NH
    int h = idx & 63;
    int bl = idx >> 6;
    float v = g_zx[(size_t)bl * DINn + (HIDC + CONVD) + h] + dt_bias[h];
    float d = (v > 20.f) ? v : log1pf(expf(v));
    g_dt[idx] = d;
}

// ---------------- per-chunk cumsum of dt*A ----------------
__global__ void cum_kernel(const float* __restrict__ A_log) {
    int ch = blockIdx.x;       // 0..63
    int h = threadIdx.x;       // 0..63
    float A = -expf(A_log[h]);
    float run = 0.f;
    for (int q = 0; q < QC; q++) {
        int r = (ch * QC + q) * NHh + h;
        run += g_dt[r] * A;
        g_cum[r] = run;
    }
}

// ---------------- per-chunk CB[i][j] = sum_n C[i,n]*B[j,n] ----------------
__global__ void __launch_bounds__(256) cb_kernel() {
    extern __shared__ float sh[];
    float* Bsh = sh;             // 128 x 129
    float* Csh = sh + 16512;     // 128 x 129
    int ch = blockIdx.x;
    int tid = threadIdx.x;
    for (int idx = tid; idx < 16384; idx += 256) {
        int i = idx >> 7, n = idx & 127;
        size_t row = (size_t)(ch * QC + i) * CONVD;
        Bsh[i * 129 + n] = g_conv[row + HIDC + n];
        Csh[i * 129 + n] = g_conv[row + HIDC + NS + n];
    }
    __syncthreads();
    int tx = tid & 15, ty = tid >> 4;
    float acc[8][8];
    #pragma unroll
    for (int i = 0; i < 8; i++)
        #pragma unroll
        for (int j = 0; j < 8; j++) acc[i][j] = 0.f;
    for (int n = 0; n < NS; n++) {
        float a[8], b[8];
        #pragma unroll
        for (int u = 0; u < 8; u++) a[u] = Csh[(ty * 8 + u) * 129 + n];
        #pragma unroll
        for (int u = 0; u < 8; u++) b[u] = Bsh[(tx * 8 + u) * 129 + n];
        #pragma unroll
        for (int i = 0; i < 8; i++)
            #pragma unroll
            for (int j = 0; j < 8; j++) acc[i][j] += a[i] * b[j];
    }
    #pragma unroll
    for (int i = 0; i < 8; i++)
        #pragma unroll
        for (int j0 = 0; j0 < 8; j0 += 4)
            *reinterpret_cast<float4*>(&g_CB[ch * 16384 + (ty * 8 + i) * 128 + tx * 8 + j0]) =
                make_float4(acc[i][j0], acc[i][j0 + 1], acc[i][j0 + 2], acc[i][j0 + 3]);
}

// ---------------- chunk states: states[h,p,n] = sum_q wdec[q]*xs[q,p]*B[q,n] ----------------
__global__ void __launch_bounds__(256) states_kernel() {
    __shared__ float Bs[32 * 128];
    __shared__ float xss[32 * 64];
    __shared__ float wdec[128];
    __shared__ float cl;
    const int h = blockIdx.x, ch = blockIdx.y;
    const int tid = threadIdx.x;
    if (tid == 0) cl = g_cum[(ch * QC + QC - 1) * NHh + h];
    __syncthreads();
    if (tid < 128) {
        int r = (ch * QC + tid) * NHh + h;
        wdec[tid] = __expf(cl - g_cum[r]) * g_dt[r];
    }
    const int p = tid >> 2, ng = tid & 3;
    float4 acc4[8];
    #pragma unroll
    for (int u = 0; u < 8; u++) acc4[u] = make_float4(0.f, 0.f, 0.f, 0.f);

    for (int qt = 0; qt < 4; qt++) {
        __syncthreads();
        for (int idx = tid; idx < 4096; idx += 256) {
            int qq = idx >> 7, n = idx & 127;
            Bs[idx] = g_conv[(size_t)(ch * QC + qt * 32 + qq) * CONVD + HIDC + n];
        }
        for (int idx = tid; idx < 2048; idx += 256) {
            int qq = idx >> 6, pp = idx & 63;
            xss[idx] = g_conv[(size_t)(ch * QC + qt * 32 + qq) * CONVD + h * PD + pp];
        }
        __syncthreads();
        #pragma unroll 4
        for (int qq = 0; qq < 32; qq++) {
            float coef = wdec[qt * 32 + qq] * xss[qq * 64 + p];
            const float4* bp = (const float4*)&Bs[qq * 128 + ng * 32];
            #pragma unroll
            for (int u = 0; u < 8; u++) fma4(acc4[u], coef, bp[u]);
        }
    }
    size_t base = ((size_t)ch * NHh + h) * (PD * NS) + (size_t)p * NS + ng * 32;
    #pragma unroll
    for (int u = 0; u < 8; u++)
        *reinterpret_cast<float4*>(&g_states[base + u * 4]) = acc4[u];
}

// ---------------- sequential inter-chunk scan (in-place: states -> Sprev) ----------------
__global__ void __launch_bounds__(256) scan_kernel() {
    const int h = blockIdx.x, b = blockIdx.y;
    const int t = threadIdx.x;
    float S[32];
    #pragma unroll
    for (int i = 0; i < 32; i++) S[i] = 0.f;
    for (int c = 0; c < 32; c++) {
        int ch = b * 32 + c;
        float dec = __expf(g_cum[(ch * QC + QC - 1) * NHh + h]);
        size_t base = ((size_t)ch * NHh + h) * (PD * NS);
        #pragma unroll
        for (int i = 0; i < 32; i++) {
            size_t id = base + (size_t)i * 256 + t;
            float st = g_states[id];
            g_states[id] = S[i];               // Sprev (state before this chunk)
            S[i] = S[i] * dec + st;
        }
    }
}

// ---------------- Yd + Yoff + D*xs -> y ----------------
__global__ void __launch_bounds__(256) ydyoff_kernel(const float* __restrict__ Dvec) {
    extern __shared__ float sh[];
    float* CBs   = sh;                 // 128 x 129
    float* Cs    = sh + 16512;         // 128 x 129
    float* SpT   = sh + 33024;         // [n][p] 128 x 64
    float* xss   = sh + 41216;         // [j][p] 128 x 64
    float* cum_s = sh + 49408;         // 128
    float* dt_s  = sh + 49536;         // 128
    const int h = blockIdx.x, ch = blockIdx.y, tid = threadIdx.x;

    for (int idx = tid; idx < 16384; idx += 256) {
        int i = idx >> 7, j = idx & 127;
        CBs[i * 129 + j] = g_CB[ch * 16384 + idx];
        Cs[i * 129 + j]  = g_conv[(size_t)(ch * QC + i) * CONVD + HIDC + NS + j];
    }
    for (int idx = tid; idx < 8192; idx += 256) {
        int p = idx >> 7, n = idx & 127;
        SpT[n * 64 + p] = g_states[((size_t)ch * NHh + h) * (PD * NS) + idx];
        xss[idx] = g_conv[(size_t)(ch * QC + (idx >> 6)) * CONVD + h * PD + (idx & 63)];
    }
    if (tid < 128) {
        int r = (ch * QC + tid) * NHh + h;
        cum_s[tid] = g_cum[r];
        dt_s[tid]  = g_dt[r];
    }
    __syncthreads();

    const int i = tid >> 1, ph = tid & 1;
    float4 aD[8], aO[8];
    #pragma unroll
    for (int u = 0; u < 8; u++) { aD[u] = make_float4(0.f,0.f,0.f,0.f); aO[u] = make_float4(0.f,0.f,0.f,0.f); }
    const float ci = cum_s[i];

    // intra-chunk (lower-triangular) attention
    for (int j = 0; j <= i; j++) {
        float m = CBs[i * 129 + j] * __expf(ci - cum_s[j]) * dt_s[j];
        const float4* xr = (const float4*)&xss[j * 64 + ph * 32];
        #pragma unroll
        for (int u = 0; u < 8; u++) fma4(aD[u], m, xr[u]);
    }
    // carried-state contribution
    #pragma unroll 4
    for (int n = 0; n < NS; n++) {
        float cv = Cs[i * 129 + n];
        const float4* sr = (const float4*)&SpT[n * 64 + ph * 32];
        #pragma unroll
        for (int u = 0; u < 8; u++) fma4(aO[u], cv, sr[u]);
    }
    const float ei = __expf(ci);
    const float Dh = Dvec[h];
    const float* xi = &xss[i * 64 + ph * 32];
    float* yo = &g_y[(size_t)(ch * QC + i) * HIDC + h * PD + ph * 32];
    #pragma unroll
    for (int u = 0; u < 8; u++) {
        float4 d = aD[u], o = aO[u];
        float4 r;
        r.x = d.x + ei * o.x + Dh * xi[u * 4 + 0];
        r.y = d.y + ei * o.y + Dh * xi[u * 4 + 1];
        r.z = d.z + ei * o.z + Dh * xi[u * 4 + 2];
        r.w = d.w + ei * o.w + Dh * xi[u * 4 + 3];
        *reinterpret_cast<float4*>(&yo[u * 4]) = r;
    }
}

// ---------------- gate with silu(z) + RMSNorm (in-place on g_y) ----------------
__global__ void __launch_bounds__(256) gating_kernel(const float* __restrict__ norm_w) {
    __shared__ float red[256];
    const int bl = blockIdx.x, tid = threadIdx.x;
    float vals[16];
    float ss = 0.f;
    #pragma unroll
    for (int it = 0; it < 16; it++) {
        int idx = it * 256 + tid;
        float yv = g_y[(size_t)bl * HIDC + idx];
        float z  = g_zx[(size_t)bl * DINn + idx];
        float yz = yv * (z / (1.f + expf(-z)));
        vals[it] = yz;
        ss += yz * yz;
    }
    red[tid] = ss;
    __syncthreads();
    for (int s = 128; s > 0; s >>= 1) {
        if (tid < s) red[tid] += red[tid + s];
        __syncthreads();
    }
    float sc = rsqrtf(red[0] / (float)HIDC + 1e-5f);
    #pragma unroll
    for (int it = 0; it < 16; it++) {
        int idx = it * 256 + tid;
        g_y[(size_t)bl * HIDC + idx] = vals[it] * sc * norm_w[idx];
    }
}

// ---------------- launch ----------------
extern "C" void kernel_launch(void* const* d_in, const int* in_sizes, int n_in,
                              void* d_out, int out_size) {
    const float* x       = (const float*)d_in[0];
    const float* W_in    = (const float*)d_in[1];
    const float* conv_w  = (const float*)d_in[2];
    const float* dt_bias = (const float*)d_in[3];
    const float* A_log   = (const float*)d_in[4];
    const float* Dv      = (const float*)d_in[5];
    const float* norm_w  = (const float*)d_in[6];
    const float* W_out   = (const float*)d_in[7];
    float* out = (float*)d_out;

    float *zx_p, *y_p;
    cudaGetSymbolAddress((void**)&zx_p, g_zx);
    cudaGetSymbolAddress((void**)&y_p, g_y);

    cudaFuncSetAttribute(gemm_tc_kernel, cudaFuncAttributeMaxDynamicSharedMemorySize, GTC_SMEM);
    cudaFuncSetAttribute(cb_kernel, cudaFuncAttributeMaxDynamicSharedMemorySize, 132096);
    cudaFuncSetAttribute(ydyoff_kernel, cudaFuncAttributeMaxDynamicSharedMemorySize, 198656);

    // 1) in-proj GEMM: (8192 x 2048) * (8512 x 2048)^T  [tf32 mma.sync]
    gemm_tc_kernel<<<dim3(67, 32), 256, GTC_SMEM>>>(x, W_in, zx_p, BLn, DINn, DIMI);
    // 2) causal conv + silu
    conv_silu_kernel<<<(BLn * CONVD) / 256, 256>>>(conv_w);
    // 3) dt softplus
    dt_kernel<<<(BLn * NHh) / 256, 256>>>(dt_bias);
    // 4) per-chunk cumsum of dt*A
    cum_kernel<<<NCT, NHh>>>(A_log);
    // 5) per-chunk CB gram
    cb_kernel<<<NCT, 256, 132096>>>();
    // 6) chunk states
    states_kernel<<<dim3(NHh, NCT), 256>>>();
    // 7) inter-chunk scan -> Sprev
    scan_kernel<<<dim3(NHh, 2), 256>>>();
    // 8) Yd + Yoff + D*xs
    ydyoff_kernel<<<dim3(NHh, NCT), 256, 198656>>>(Dv);
    // 9) gate + rmsnorm
    gating_kernel<<<BLn, 256>>>(norm_w);
    // 10) out-proj GEMM: (8192 x 4096) * (2048 x 4096)^T  [tf32 mma.sync]
    gemm_tc_kernel<<<dim3(16, 32), 256, GTC_SMEM>>>(y_p, W_out, out, BLn, DIMI, HIDC);
}

// round 4
// speedup vs baseline: 1.8358x; 1.0387x over previous
#include <cuda_runtime.h>
#include <cstdint>

// ---------------- problem constants ----------------
#define BLn    8192      // B * L
#define LSEQ   4096
#define DIMI   2048
#define DINn   8512      // 2*HID + 2*G*N + H
#define HIDC   4096
#define CONVD  4352      // HID + 2*G*N
#define NHh    64        // heads
#define PD     64        // head dim
#define NS     128       // state dim
#define QC     128       // chunk len
#define NCT    64        // total chunks = B * (L/Q)

// ---------------- scratch (device globals; allocation-free rule) ----------------
__device__ float g_zx[(size_t)BLn * DINn];        // in-proj output (z | xBC | dt_raw)
__device__ float g_conv[(size_t)BLn * CONVD];     // conv+silu output (xs | B | C)
__device__ float g_dt[BLn * NHh];                 // softplus(dt_raw + bias)
__device__ float g_cum[BLn * NHh];                // per-chunk cumsum of dt*A
__device__ float g_CB[NCT * QC * QC];             // per-chunk C.B^T gram
__device__ float g_states[(size_t)NCT * NHh * PD * NS];  // chunk states, then Sprev in-place
__device__ float g_y[(size_t)BLn * HIDC];         // y, then yn in-place

__device__ __forceinline__ void fma4(float4& a, float s, const float4 v) {
    a.x += s * v.x; a.y += s * v.y; a.z += s * v.z; a.w += s * v.w;
}

// =======================================================================
//  tf32 mma.sync GEMM with 4-stage cp.async pipeline
//  C[M,N] = A[M,K] * B[N,K]^T  (K-major fp32 in/out)
//  CTA tile 256x128, 8 warps (4x2), warp tile 64x64, K-step 16
// =======================================================================

__device__ __forceinline__ uint32_t f2tf32(uint32_t bits) {
    uint32_t r;
    asm("cvt.rna.tf32.f32 %0, %1;" : "=r"(r) : "f"(__uint_as_float(bits)));
    return r;
}

__device__ __forceinline__ void mma_tf32(float* d, const uint32_t* a, const uint32_t* b) {
    asm volatile(
        "mma.sync.aligned.m16n8k8.row.col.f32.tf32.tf32.f32 "
        "{%0,%1,%2,%3}, {%4,%5,%6,%7}, {%8,%9}, {%0,%1,%2,%3};"
        : "+f"(d[0]), "+f"(d[1]), "+f"(d[2]), "+f"(d[3])
        : "r"(a[0]), "r"(a[1]), "r"(a[2]), "r"(a[3]), "r"(b[0]), "r"(b[1]));
}

__device__ __forceinline__ uint32_t smem_u32(const void* p) {
    uint32_t a;
    asm("{ .reg .u64 t; cvta.to.shared.u64 t, %1; cvt.u32.u64 %0, t; }" : "=r"(a) : "l"(p));
    return a;
}

#define ASTR  20                          // padded row stride (u32) — conflict-free
#define SSTR  ((256 + 128) * ASTR)        // per-stage floats = 7680
#define NSTG  4
#define GTC_SMEM (NSTG * SSTR * 4)        // 122880 bytes

__global__ void __launch_bounds__(256) gemm_tc_kernel(
    const float* __restrict__ A, const float* __restrict__ B, float* __restrict__ C,
    int M, int Nn, int K)
{
    extern __shared__ uint32_t sm[];
    const uint32_t smb = smem_u32(sm);
    const int tid  = threadIdx.x;
    const int wid  = tid >> 5, lane = tid & 31;
    const int gID  = lane >> 2, tig = lane & 3;
    const int wM   = (wid >> 1) * 64;
    const int wN   = (wid & 1) * 64;
    const int cRow = blockIdx.y * 256;
    const int cCol = blockIdx.x * 128;
    const int KT   = K >> 4;

    // per-thread staging coords
    const int arow[4] = { (0*256+tid)>>2, (1*256+tid)>>2, (2*256+tid)>>2, (3*256+tid)>>2 };
    const int ac4  = (tid & 3) * 4;
    const int brow[2] = { (0*256+tid)>>2, (1*256+tid)>>2 };
    const bool bok[2] = { cCol + brow[0] < Nn, cCol + brow[1] < Nn };

    float acc[4][8][4];
    #pragma unroll
    for (int mi = 0; mi < 4; mi++)
        #pragma unroll
        for (int ni = 0; ni < 8; ni++)
            #pragma unroll
            for (int u = 0; u < 4; u++) acc[mi][ni][u] = 0.f;

    // issue one stage of cp.async loads
    auto issue_stage = [&](int kt, int slot) {
        const int kb = kt << 4;
        const uint32_t as = smb + (uint32_t)slot * SSTR * 4;
        const uint32_t bs = as + 256 * ASTR * 4;
        #pragma unroll
        for (int v = 0; v < 4; v++) {
            const float* gp = A + (size_t)(cRow + arow[v]) * K + kb + ac4;
            uint32_t sa = as + (arow[v] * ASTR + ac4) * 4;
            asm volatile("cp.async.cg.shared.global [%0], [%1], 16;" :: "r"(sa), "l"(gp));
        }
        #pragma unroll
        for (int v = 0; v < 2; v++) {
            const float* gp = bok[v] ? (B + (size_t)(cCol + brow[v]) * K + kb + ac4) : B;
            const int ssz = bok[v] ? 16 : 0;
            uint32_t sa = bs + (brow[v] * ASTR + ac4) * 4;
            asm volatile("cp.async.cg.shared.global [%0], [%1], 16, %2;" :: "r"(sa), "l"(gp), "r"(ssz));
        }
        asm volatile("cp.async.commit_group;" ::: "memory");
    };

    issue_stage(0, 0);
    issue_stage(1, 1);
    issue_stage(2, 2);

    for (int kt = 0; kt < KT; kt++) {
        asm volatile("cp.async.wait_group 2;" ::: "memory");
        __syncthreads();
        if (kt + 3 < KT) issue_stage(kt + 3, (kt + 3) & 3);
        else asm volatile("cp.async.commit_group;" ::: "memory");

        const uint32_t* As = sm + (kt & 3) * SSTR;
        const uint32_t* Bs = As + 256 * ASTR;
        #pragma unroll
        for (int kk = 0; kk < 2; kk++) {
            uint32_t af[4][4], bf[8][2];
            const int col = kk * 8 + tig;
            #pragma unroll
            for (int mi = 0; mi < 4; mi++) {
                const int r = wM + mi * 16 + gID;
                af[mi][0] = f2tf32(As[r * ASTR + col]);
                af[mi][1] = f2tf32(As[(r + 8) * ASTR + col]);
                af[mi][2] = f2tf32(As[r * ASTR + col + 4]);
                af[mi][3] = f2tf32(As[(r + 8) * ASTR + col + 4]);
            }
            #pragma unroll
            for (int ni = 0; ni < 8; ni++) {
                const int r = wN + ni * 8 + gID;
                bf[ni][0] = f2tf32(Bs[r * ASTR + col]);
                bf[ni][1] = f2tf32(Bs[r * ASTR + col + 4]);
            }
            #pragma unroll
            for (int mi = 0; mi < 4; mi++)
                #pragma unroll
                for (int ni = 0; ni < 8; ni++)
                    mma_tf32(acc[mi][ni], af[mi], bf[ni]);
        }
    }

    // epilogue: direct gmem stores
    #pragma unroll
    for (int mi = 0; mi < 4; mi++) {
        const int r0 = cRow + wM + mi * 16 + gID;
        #pragma unroll
        for (int ni = 0; ni < 8; ni++) {
            const int c = cCol + wN + ni * 8 + tig * 2;
            if (c < Nn) {
                *reinterpret_cast<float2*>(C + (size_t)r0 * Nn + c) =
                    make_float2(acc[mi][ni][0], acc[mi][ni][1]);
                *reinterpret_cast<float2*>(C + (size_t)(r0 + 8) * Nn + c) =
                    make_float2(acc[mi][ni][2], acc[mi][ni][3]);
            }
        }
    }
}

// ---------------- causal depthwise conv (K=4) + SiLU ----------------
__global__ void __launch_bounds__(256) conv_silu_kernel(const float* __restrict__ w) {
    size_t idx = (size_t)blockIdx.x * 256 + threadIdx.x;   // over BL*CONVD
    int c = (int)(idx % CONVD);
    int bl = (int)(idx / CONVD);
    int l = bl & (LSEQ - 1);
    float acc = 0.f;
    #pragma unroll
    for (int k = 0; k < 4; k++) {
        int lo = l - 3 + k;
        if (lo >= 0)
            acc += g_zx[(size_t)(bl - 3 + k) * DINn + HIDC + c] * w[c * 4 + k];
    }
    float s = 1.f / (1.f + expf(-acc));
    g_conv[(size_t)bl * CONVD + c] = acc * s;
}

// ---------------- dt = softplus(dt_raw + bias) ----------------
__global__ void __launch_bounds__(256) dt_kernel(const float* __restrict__ dt_bias) {
    int idx = blockIdx.x * 256 + threadIdx.x;    // over BL*NH
    int h = idx & 63;
    int bl = idx >> 6;
    float v = g_zx[(size_t)bl * DINn + (HIDC + CONVD) + h] + dt_bias[h];
    float d = (v > 20.f) ? v : log1pf(expf(v));
    g_dt[idx] = d;
}

// ---------------- per-chunk cumsum of dt*A ----------------
__global__ void cum_kernel(const float* __restrict__ A_log) {
    int ch = blockIdx.x;       // 0..63
    int h = threadIdx.x;       // 0..63
    float A = -expf(A_log[h]);
    float run = 0.f;
    for (int q = 0; q < QC; q++) {
        int r = (ch * QC + q) * NHh + h;
        run += g_dt[r] * A;
        g_cum[r] = run;
    }
}

// ---------------- per-chunk CB[i][j] = sum_n C[i,n]*B[j,n] ----------------
__global__ void __launch_bounds__(256) cb_kernel() {
    extern __shared__ float sh[];
    float* Bsh = sh;             // 128 x 129
    float* Csh = sh + 16512;     // 128 x 129
    int ch = blockIdx.x;
    int tid = threadIdx.x;
    for (int idx = tid; idx < 16384; idx += 256) {
        int i = idx >> 7, n = idx & 127;
        size_t row = (size_t)(ch * QC + i) * CONVD;
        Bsh[i * 129 + n] = g_conv[row + HIDC + n];
        Csh[i * 129 + n] = g_conv[row + HIDC + NS + n];
    }
    __syncthreads();
    int tx = tid & 15, ty = tid >> 4;
    float acc[8][8];
    #pragma unroll
    for (int i = 0; i < 8; i++)
        #pragma unroll
        for (int j = 0; j < 8; j++) acc[i][j] = 0.f;
    for (int n = 0; n < NS; n++) {
        float a[8], b[8];
        #pragma unroll
        for (int u = 0; u < 8; u++) a[u] = Csh[(ty * 8 + u) * 129 + n];
        #pragma unroll
        for (int u = 0; u < 8; u++) b[u] = Bsh[(tx * 8 + u) * 129 + n];
        #pragma unroll
        for (int i = 0; i < 8; i++)
            #pragma unroll
            for (int j = 0; j < 8; j++) acc[i][j] += a[i] * b[j];
    }
    #pragma unroll
    for (int i = 0; i < 8; i++)
        #pragma unroll
        for (int j0 = 0; j0 < 8; j0 += 4)
            *reinterpret_cast<float4*>(&g_CB[ch * 16384 + (ty * 8 + i) * 128 + tx * 8 + j0]) =
                make_float4(acc[i][j0], acc[i][j0 + 1], acc[i][j0 + 2], acc[i][j0 + 3]);
}

// ---------------- chunk states: states[h,p,n] = sum_q wdec[q]*xs[q,p]*B[q,n] ----------------
__global__ void __launch_bounds__(256) states_kernel() {
    __shared__ float Bs[32 * 128];
    __shared__ float xss[32 * 64];
    __shared__ float wdec[128];
    __shared__ float cl;
    const int h = blockIdx.x, ch = blockIdx.y;
    const int tid = threadIdx.x;
    if (tid == 0) cl = g_cum[(ch * QC + QC - 1) * NHh + h];
    __syncthreads();
    if (tid < 128) {
        int r = (ch * QC + tid) * NHh + h;
        wdec[tid] = __expf(cl - g_cum[r]) * g_dt[r];
    }
    const int p = tid >> 2, ng = tid & 3;
    float4 acc4[8];
    #pragma unroll
    for (int u = 0; u < 8; u++) acc4[u] = make_float4(0.f, 0.f, 0.f, 0.f);

    for (int qt = 0; qt < 4; qt++) {
        __syncthreads();
        for (int idx = tid; idx < 4096; idx += 256) {
            int qq = idx >> 7, n = idx & 127;
            Bs[idx] = g_conv[(size_t)(ch * QC + qt * 32 + qq) * CONVD + HIDC + n];
        }
        for (int idx = tid; idx < 2048; idx += 256) {
            int qq = idx >> 6, pp = idx & 63;
            xss[idx] = g_conv[(size_t)(ch * QC + qt * 32 + qq) * CONVD + h * PD + pp];
        }
        __syncthreads();
        #pragma unroll 4
        for (int qq = 0; qq < 32; qq++) {
            float coef = wdec[qt * 32 + qq] * xss[qq * 64 + p];
            const float4* bp = (const float4*)&Bs[qq * 128 + ng * 32];
            #pragma unroll
            for (int u = 0; u < 8; u++) fma4(acc4[u], coef, bp[u]);
        }
    }
    size_t base = ((size_t)ch * NHh + h) * (PD * NS) + (size_t)p * NS + ng * 32;
    #pragma unroll
    for (int u = 0; u < 8; u++)
        *reinterpret_cast<float4*>(&g_states[base + u * 4]) = acc4[u];
}

// ---------------- sequential inter-chunk scan (in-place: states -> Sprev) ----------------
__global__ void __launch_bounds__(256) scan_kernel() {
    const int h = blockIdx.x, b = blockIdx.y;
    const int t = threadIdx.x;
    float S[32];
    #pragma unroll
    for (int i = 0; i < 32; i++) S[i] = 0.f;
    for (int c = 0; c < 32; c++) {
        int ch = b * 32 + c;
        float dec = __expf(g_cum[(ch * QC + QC - 1) * NHh + h]);
        size_t base = ((size_t)ch * NHh + h) * (PD * NS);
        #pragma unroll
        for (int i = 0; i < 32; i++) {
            size_t id = base + (size_t)i * 256 + t;
            float st = g_states[id];
            g_states[id] = S[i];               // Sprev (state before this chunk)
            S[i] = S[i] * dec + st;
        }
    }
}

// ---------------- Yd + Yoff + D*xs -> y ----------------
__global__ void __launch_bounds__(256) ydyoff_kernel(const float* __restrict__ Dvec) {
    extern __shared__ float sh[];
    float* CBs   = sh;                 // 128 x 129
    float* Cs    = sh + 16512;         // 128 x 129
    float* SpT   = sh + 33024;         // [n][p] 128 x 64
    float* xss   = sh + 41216;         // [j][p] 128 x 64
    float* cum_s = sh + 49408;         // 128
    float* dt_s  = sh + 49536;         // 128
    const int h = blockIdx.x, ch = blockIdx.y, tid = threadIdx.x;

    for (int idx = tid; idx < 16384; idx += 256) {
        int i = idx >> 7, j = idx & 127;
        CBs[i * 129 + j] = g_CB[ch * 16384 + idx];
        Cs[i * 129 + j]  = g_conv[(size_t)(ch * QC + i) * CONVD + HIDC + NS + j];
    }
    for (int idx = tid; idx < 8192; idx += 256) {
        int p = idx >> 7, n = idx & 127;
        SpT[n * 64 + p] = g_states[((size_t)ch * NHh + h) * (PD * NS) + idx];
        xss[idx] = g_conv[(size_t)(ch * QC + (idx >> 6)) * CONVD + h * PD + (idx & 63)];
    }
    if (tid < 128) {
        int r = (ch * QC + tid) * NHh + h;
        cum_s[tid] = g_cum[r];
        dt_s[tid]  = g_dt[r];
    }
    __syncthreads();

    const int i = tid >> 1, ph = tid & 1;
    float4 aD[8], aO[8];
    #pragma unroll
    for (int u = 0; u < 8; u++) { aD[u] = make_float4(0.f,0.f,0.f,0.f); aO[u] = make_float4(0.f,0.f,0.f,0.f); }
    const float ci = cum_s[i];

    // intra-chunk (lower-triangular) attention
    for (int j = 0; j <= i; j++) {
        float m = CBs[i * 129 + j] * __expf(ci - cum_s[j]) * dt_s[j];
        const float4* xr = (const float4*)&xss[j * 64 + ph * 32];
        #pragma unroll
        for (int u = 0; u < 8; u++) fma4(aD[u], m, xr[u]);
    }
    // carried-state contribution
    #pragma unroll 4
    for (int n = 0; n < NS; n++) {
        float cv = Cs[i * 129 + n];
        const float4* sr = (const float4*)&SpT[n * 64 + ph * 32];
        #pragma unroll
        for (int u = 0; u < 8; u++) fma4(aO[u], cv, sr[u]);
    }
    const float ei = __expf(ci);
    const float Dh = Dvec[h];
    const float* xi = &xss[i * 64 + ph * 32];
    float* yo = &g_y[(size_t)(ch * QC + i) * HIDC + h * PD + ph * 32];
    #pragma unroll
    for (int u = 0; u < 8; u++) {
        float4 d = aD[u], o = aO[u];
        float4 r;
        r.x = d.x + ei * o.x + Dh * xi[u * 4 + 0];
        r.y = d.y + ei * o.y + Dh * xi[u * 4 + 1];
        r.z = d.z + ei * o.z + Dh * xi[u * 4 + 2];
        r.w = d.w + ei * o.w + Dh * xi[u * 4 + 3];
        *reinterpret_cast<float4*>(&yo[u * 4]) = r;
    }
}

// ---------------- gate with silu(z) + RMSNorm (in-place on g_y) ----------------
__global__ void __launch_bounds__(256) gating_kernel(const float* __restrict__ norm_w) {
    __shared__ float red[256];
    const int bl = blockIdx.x, tid = threadIdx.x;
    float vals[16];
    float ss = 0.f;
    #pragma unroll
    for (int it = 0; it < 16; it++) {
        int idx = it * 256 + tid;
        float yv = g_y[(size_t)bl * HIDC + idx];
        float z  = g_zx[(size_t)bl * DINn + idx];
        float yz = yv * (z / (1.f + expf(-z)));
        vals[it] = yz;
        ss += yz * yz;
    }
    red[tid] = ss;
    __syncthreads();
    for (int s = 128; s > 0; s >>= 1) {
        if (tid < s) red[tid] += red[tid + s];
        __syncthreads();
    }
    float sc = rsqrtf(red[0] / (float)HIDC + 1e-5f);
    #pragma unroll
    for (int it = 0; it < 16; it++) {
        int idx = it * 256 + tid;
        g_y[(size_t)bl * HIDC + idx] = vals[it] * sc * norm_w[idx];
    }
}

// ---------------- launch ----------------
extern "C" void kernel_launch(void* const* d_in, const int* in_sizes, int n_in,
                              void* d_out, int out_size) {
    const float* x       = (const float*)d_in[0];
    const float* W_in    = (const float*)d_in[1];
    const float* conv_w  = (const float*)d_in[2];
    const float* dt_bias = (const float*)d_in[3];
    const float* A_log   = (const float*)d_in[4];
    const float* Dv      = (const float*)d_in[5];
    const float* norm_w  = (const float*)d_in[6];
    const float* W_out   = (const float*)d_in[7];
    float* out = (float*)d_out;

    float *zx_p, *y_p;
    cudaGetSymbolAddress((void**)&zx_p, g_zx);
    cudaGetSymbolAddress((void**)&y_p, g_y);

    cudaFuncSetAttribute(gemm_tc_kernel, cudaFuncAttributeMaxDynamicSharedMemorySize, GTC_SMEM);
    cudaFuncSetAttribute(cb_kernel, cudaFuncAttributeMaxDynamicSharedMemorySize, 132096);
    cudaFuncSetAttribute(ydyoff_kernel, cudaFuncAttributeMaxDynamicSharedMemorySize, 198656);

    // 1) in-proj GEMM: (8192 x 2048) * (8512 x 2048)^T  [tf32 mma.sync + cp.async]
    gemm_tc_kernel<<<dim3(67, 32), 256, GTC_SMEM>>>(x, W_in, zx_p, BLn, DINn, DIMI);
    // 2) causal conv + silu
    conv_silu_kernel<<<(BLn * CONVD) / 256, 256>>>(conv_w);
    // 3) dt softplus
    dt_kernel<<<(BLn * NHh) / 256, 256>>>(dt_bias);
    // 4) per-chunk cumsum of dt*A
    cum_kernel<<<NCT, NHh>>>(A_log);
    // 5) per-chunk CB gram
    cb_kernel<<<NCT, 256, 132096>>>();
    // 6) chunk states
    states_kernel<<<dim3(NHh, NCT), 256>>>();
    // 7) inter-chunk scan -> Sprev
    scan_kernel<<<dim3(NHh, 2), 256>>>();
    // 8) Yd + Yoff + D*xs
    ydyoff_kernel<<<dim3(NHh, NCT), 256, 198656>>>(Dv);
    // 9) gate + rmsnorm
    gating_kernel<<<BLn, 256>>>(norm_w);
    // 10) out-proj GEMM: (8192 x 4096) * (2048 x 4096)^T  [tf32 mma.sync + cp.async]
    gemm_tc_kernel<<<dim3(16, 32), 256, GTC_SMEM>>>(y_p, W_out, out, BLn, DIMI, HIDC);
}

// round 6
// speedup vs baseline: 1.9034x; 1.0368x over previous
#include <cuda_runtime.h>
#include <cuda_fp16.h>
#include <cstdint>

// ---------------- problem constants ----------------
#define BLn    8192      // B * L
#define LSEQ   4096
#define DIMI   2048
#define DINn   8512      // 2*HID + 2*G*N + H
#define HIDC   4096
#define CONVD  4352      // HID + 2*G*N
#define NHh    64        // heads
#define PD     64        // head dim
#define NS     128       // state dim
#define QC     128       // chunk len
#define NCT    64        // total chunks = B * (L/Q)

// ---------------- scratch (device globals; allocation-free rule) ----------------
__device__ float g_zx[(size_t)BLn * DINn];        // in-proj output (z | xBC | dt_raw)
__device__ float g_conv[(size_t)BLn * CONVD];     // conv+silu output (xs | B | C)
__device__ float g_dt[BLn * NHh];                 // softplus(dt_raw + bias)
__device__ float g_cum[BLn * NHh];                // per-chunk cumsum of dt*A
__device__ float g_CB[NCT * QC * QC];             // per-chunk C.B^T gram
__device__ float g_states[(size_t)NCT * NHh * PD * NS];  // chunk states, then Sprev in-place
__device__ float g_y[(size_t)BLn * HIDC];         // y, then yn in-place

__device__ __forceinline__ void fma4(float4& a, float s, const float4 v) {
    a.x += s * v.x; a.y += s * v.y; a.z += s * v.z; a.w += s * v.w;
}

// =======================================================================
//  fp16 mma.sync m16n8k16 GEMM:  C[M,N] = A[M,K] * B[N,K]^T
//  fp32 in/out, fp16 operands (11-bit mantissa == tf32), fp32 accum.
//  CTA tile 256x128, 8 warps (4x2), warp tile 64x64, K-step 16, dbl-buffer
// =======================================================================

// pack two floats into half2 (lo = x, hi = y)
__device__ __forceinline__ uint32_t pack_h2(float x, float y) {
    uint32_t r;
    asm("cvt.rn.f16x2.f32 %0, %1, %2;" : "=r"(r) : "f"(y), "f"(x));
    return r;
}

__device__ __forceinline__ void mma_f16(float* d, const uint32_t* a, const uint32_t* b) {
    asm volatile(
        "mma.sync.aligned.m16n8k16.row.col.f32.f16.f16.f32 "
        "{%0,%1,%2,%3}, {%4,%5,%6,%7}, {%8,%9}, {%0,%1,%2,%3};"
        : "+f"(d[0]), "+f"(d[1]), "+f"(d[2]), "+f"(d[3])
        : "r"(a[0]), "r"(a[1]), "r"(a[2]), "r"(a[3]), "r"(b[0]), "r"(b[1]));
}

#define AH    20                              // half stride per smem row (16 + pad 4)
#define SSTH  ((256 + 128) * AH)              // halfs per stage = 7680
#define GTC_SMEM (2 * SSTH * 2)               // 30720 bytes

__global__ void __launch_bounds__(256) gemm_tc_kernel(
    const float* __restrict__ A, const float* __restrict__ B, float* __restrict__ C,
    int M, int Nn, int K)
{
    extern __shared__ __half hsm[];
    const int tid  = threadIdx.x;
    const int wid  = tid >> 5, lane = tid & 31;
    const int gID  = lane >> 2, tig = lane & 3;
    const int wM   = (wid >> 1) * 64;
    const int wN   = (wid & 1) * 64;
    const int cRow = blockIdx.y * 256;
    const int cCol = blockIdx.x * 128;
    const int KT   = K >> 4;

    // staging coords: i = v*256+tid -> row i>>2, 4 floats at (i&3)*4
    const int srow = tid >> 2;
    const int sc4  = (tid & 3) * 4;
    const bool bok0 = cCol + srow < Nn;
    const bool bok1 = cCol + 64 + srow < Nn;

    float acc[4][8][4];
    #pragma unroll
    for (int mi = 0; mi < 4; mi++)
        #pragma unroll
        for (int ni = 0; ni < 8; ni++)
            #pragma unroll
            for (int u = 0; u < 4; u++) acc[mi][ni][u] = 0.f;

    auto store_stage = [&](int slot, const float4* ra, const float4* rb) {
        __half* As = hsm + slot * SSTH;
        __half* Bs = As + 256 * AH;
        #pragma unroll
        for (int v = 0; v < 4; v++) {
            uint2 pk = make_uint2(pack_h2(ra[v].x, ra[v].y), pack_h2(ra[v].z, ra[v].w));
            *reinterpret_cast<uint2*>(&As[(v * 64 + srow) * AH + sc4]) = pk;
        }
        #pragma unroll
        for (int v = 0; v < 2; v++) {
            uint2 pk = make_uint2(pack_h2(rb[v].x, rb[v].y), pack_h2(rb[v].z, rb[v].w));
            *reinterpret_cast<uint2*>(&Bs[(v * 64 + srow) * AH + sc4]) = pk;
        }
    };

    float4 ra[4], rb[2];
    // prologue: tile 0
    {
        #pragma unroll
        for (int v = 0; v < 4; v++)
            ra[v] = *reinterpret_cast<const float4*>(A + (size_t)(cRow + v * 64 + srow) * K + sc4);
        rb[0] = bok0 ? *reinterpret_cast<const float4*>(B + (size_t)(cCol + srow) * K + sc4)
                     : make_float4(0.f, 0.f, 0.f, 0.f);
        rb[1] = bok1 ? *reinterpret_cast<const float4*>(B + (size_t)(cCol + 64 + srow) * K + sc4)
                     : make_float4(0.f, 0.f, 0.f, 0.f);
        store_stage(0, ra, rb);
    }
    __syncthreads();

    for (int kt = 0; kt < KT; kt++) {
        const int b = kt & 1;
        const bool more = (kt + 1 < KT);
        if (more) {
            const int kb = (kt + 1) << 4;
            #pragma unroll
            for (int v = 0; v < 4; v++)
                ra[v] = *reinterpret_cast<const float4*>(A + (size_t)(cRow + v * 64 + srow) * K + kb + sc4);
            rb[0] = bok0 ? *reinterpret_cast<const float4*>(B + (size_t)(cCol + srow) * K + kb + sc4)
                         : make_float4(0.f, 0.f, 0.f, 0.f);
            rb[1] = bok1 ? *reinterpret_cast<const float4*>(B + (size_t)(cCol + 64 + srow) * K + kb + sc4)
                         : make_float4(0.f, 0.f, 0.f, 0.f);
        }

        // compute on stage b
        const __half* As = hsm + b * SSTH;
        const __half* Bs = As + 256 * AH;
        const int k0 = tig * 2;
        uint32_t af[4][4], bf[8][2];
        #pragma unroll
        for (int mi = 0; mi < 4; mi++) {
            const int r = wM + mi * 16 + gID;
            af[mi][0] = *reinterpret_cast<const uint32_t*>(&As[r * AH + k0]);
            af[mi][1] = *reinterpret_cast<const uint32_t*>(&As[(r + 8) * AH + k0]);
            af[mi][2] = *reinterpret_cast<const uint32_t*>(&As[r * AH + k0 + 8]);
            af[mi][3] = *reinterpret_cast<const uint32_t*>(&As[(r + 8) * AH + k0 + 8]);
        }
        #pragma unroll
        for (int ni = 0; ni < 8; ni++) {
            const int r = wN + ni * 8 + gID;
            bf[ni][0] = *reinterpret_cast<const uint32_t*>(&Bs[r * AH + k0]);
            bf[ni][1] = *reinterpret_cast<const uint32_t*>(&Bs[r * AH + k0 + 8]);
        }
        #pragma unroll
        for (int mi = 0; mi < 4; mi++)
            #pragma unroll
            for (int ni = 0; ni < 8; ni++)
                mma_f16(acc[mi][ni], af[mi], bf[ni]);

        if (more) store_stage(b ^ 1, ra, rb);
        __syncthreads();
    }

    // epilogue: direct gmem stores
    #pragma unroll
    for (int mi = 0; mi < 4; mi++) {
        const int r0 = cRow + wM + mi * 16 + gID;
        #pragma unroll
        for (int ni = 0; ni < 8; ni++) {
            const int c = cCol + wN + ni * 8 + tig * 2;
            if (c < Nn) {
                *reinterpret_cast<float2*>(C + (size_t)r0 * Nn + c) =
                    make_float2(acc[mi][ni][0], acc[mi][ni][1]);
                *reinterpret_cast<float2*>(C + (size_t)(r0 + 8) * Nn + c) =
                    make_float2(acc[mi][ni][2], acc[mi][ni][3]);
            }
        }
    }
}

// ---------------- causal depthwise conv (K=4) + SiLU ----------------
__global__ void __launch_bounds__(256) conv_silu_kernel(const float* __restrict__ w) {
    size_t idx = (size_t)blockIdx.x * 256 + threadIdx.x;   // over BL*CONVD
    int c = (int)(idx % CONVD);
    int bl = (int)(idx / CONVD);
    int l = bl & (LSEQ - 1);
    float acc = 0.f;
    #pragma unroll
    for (int k = 0; k < 4; k++) {
        int lo = l - 3 + k;
        if (lo >= 0)
            acc += g_zx[(size_t)(bl - 3 + k) * DINn + HIDC + c] * w[c * 4 + k];
    }
    float s = 1.f / (1.f + expf(-acc));
    g_conv[(size_t)bl * CONVD + c] = acc * s;
}

// ---------------- dt = softplus(dt_raw + bias) ----------------
__global__ void __launch_bounds__(256) dt_kernel(const float* __restrict__ dt_bias) {
    int idx = blockIdx.x * 256 + threadIdx.x;    // over BL*NH
    int h = idx & 63;
    int bl = idx >> 6;
    float v = g_zx[(size_t)bl * DINn + (HIDC + CONVD) + h] + dt_bias[h];
    float d = (v > 20.f) ? v : log1pf(expf(v));
    g_dt[idx] = d;
}

// ---------------- per-chunk cumsum of dt*A (one thread per (ch,h)) ----------------
__global__ void __launch_bounds__(256) cum_kernel(const float* __restrict__ A_log) {
    int idx = blockIdx.x * 256 + threadIdx.x;   // 0..4095
    int h = idx & 63, ch = idx >> 6;
    float A = -expf(A_log[h]);
    float run = 0.f;
    for (int q = 0; q < QC; q++) {
        int r = (ch * QC + q) * NHh + h;
        run += g_dt[r] * A;
        g_cum[r] = run;
    }
}

// ---------------- per-chunk CB[i][j] = sum_n C[i,n]*B[j,n] ----------------
__global__ void __launch_bounds__(256) cb_kernel() {
    extern __shared__ float sh[];
    float* Bsh = sh;             // 128 x 129
    float* Csh = sh + 16512;     // 128 x 129
    int ch = blockIdx.x;
    int tid = threadIdx.x;
    for (int idx = tid; idx < 16384; idx += 256) {
        int i = idx >> 7, n = idx & 127;
        size_t row = (size_t)(ch * QC + i) * CONVD;
        Bsh[i * 129 + n] = g_conv[row + HIDC + n];
        Csh[i * 129 + n] = g_conv[row + HIDC + NS + n];
    }
    __syncthreads();
    int tx = tid & 15, ty = tid >> 4;
    float acc[8][8];
    #pragma unroll
    for (int i = 0; i < 8; i++)
        #pragma unroll
        for (int j = 0; j < 8; j++) acc[i][j] = 0.f;
    for (int n = 0; n < NS; n++) {
        float a[8], b[8];
        #pragma unroll
        for (int u = 0; u < 8; u++) a[u] = Csh[(ty * 8 + u) * 129 + n];
        #pragma unroll
        for (int u = 0; u < 8; u++) b[u] = Bsh[(tx * 8 + u) * 129 + n];
        #pragma unroll
        for (int i = 0; i < 8; i++)
            #pragma unroll
            for (int j = 0; j < 8; j++) acc[i][j] += a[i] * b[j];
    }
    #pragma unroll
    for (int i = 0; i < 8; i++)
        #pragma unroll
        for (int j0 = 0; j0 < 8; j0 += 4)
            *reinterpret_cast<float4*>(&g_CB[ch * 16384 + (ty * 8 + i) * 128 + tx * 8 + j0]) =
                make_float4(acc[i][j0], acc[i][j0 + 1], acc[i][j0 + 2], acc[i][j0 + 3]);
}

// ---------------- chunk states: states[h,p,n] = sum_q wdec[q]*xs[q,p]*B[q,n] ----------------
__global__ void __launch_bounds__(256) states_kernel() {
    __shared__ float Bs[32 * 128];
    __shared__ float xss[32 * 64];
    __shared__ float wdec[128];
    __shared__ float cl;
    const int h = blockIdx.x, ch = blockIdx.y;
    const int tid = threadIdx.x;
    if (tid == 0) cl = g_cum[(ch * QC + QC - 1) * NHh + h];
    __syncthreads();
    if (tid < 128) {
        int r = (ch * QC + tid) * NHh + h;
        wdec[tid] = __expf(cl - g_cum[r]) * g_dt[r];
    }
    const int p = tid >> 2, ng = tid & 3;
    float4 acc4[8];
    #pragma unroll
    for (int u = 0; u < 8; u++) acc4[u] = make_float4(0.f, 0.f, 0.f, 0.f);

    for (int qt = 0; qt < 4; qt++) {
        __syncthreads();
        for (int idx = tid; idx < 4096; idx += 256) {
            int qq = idx >> 7, n = idx & 127;
            Bs[idx] = g_conv[(size_t)(ch * QC + qt * 32 + qq) * CONVD + HIDC + n];
        }
        for (int idx = tid; idx < 2048; idx += 256) {
            int qq = idx >> 6, pp = idx & 63;
            xss[idx] = g_conv[(size_t)(ch * QC + qt * 32 + qq) * CONVD + h * PD + pp];
        }
        __syncthreads();
        #pragma unroll 4
        for (int qq = 0; qq < 32; qq++) {
            float coef = wdec[qt * 32 + qq] * xss[qq * 64 + p];
            const float4* bp = (const float4*)&Bs[qq * 128 + ng * 32];
            #pragma unroll
            for (int u = 0; u < 8; u++) fma4(acc4[u], coef, bp[u]);
        }
    }
    size_t base = ((size_t)ch * NHh + h) * (PD * NS) + (size_t)p * NS + ng * 32;
    #pragma unroll
    for (int u = 0; u < 8; u++)
        *reinterpret_cast<float4*>(&g_states[base + u * 4]) = acc4[u];
}

// ---------------- sequential inter-chunk scan (in-place: states -> Sprev) ----------------
__global__ void __launch_bounds__(256) scan_kernel() {
    const int h = blockIdx.x, b = blockIdx.y;
    const int t = threadIdx.x;
    float S[32];
    #pragma unroll
    for (int i = 0; i < 32; i++) S[i] = 0.f;
    for (int c = 0; c < 32; c++) {
        int ch = b * 32 + c;
        float dec = __expf(g_cum[(ch * QC + QC - 1) * NHh + h]);
        size_t base = ((size_t)ch * NHh + h) * (PD * NS);
        #pragma unroll
        for (int i = 0; i < 32; i++) {
            size_t id = base + (size_t)i * 256 + t;
            float st = g_states[id];
            g_states[id] = S[i];               // Sprev (state before this chunk)
            S[i] = S[i] * dec + st;
        }
    }
}

// ---------------- Yd + Yoff + D*xs -> y ----------------
__global__ void __launch_bounds__(256) ydyoff_kernel(const float* __restrict__ Dvec) {
    extern __shared__ float sh[];
    float* CBs   = sh;                 // 128 x 129
    float* Cs    = sh + 16512;         // 128 x 129
    float* SpT   = sh + 33024;         // [n][p] 128 x 64
    float* xss   = sh + 41216;         // [j][p] 128 x 64
    float* cum_s = sh + 49408;         // 128
    float* dt_s  = sh + 49536;         // 128
    const int h = blockIdx.x, ch = blockIdx.y, tid = threadIdx.x;

    for (int idx = tid; idx < 16384; idx += 256) {
        int i = idx >> 7, j = idx & 127;
        CBs[i * 129 + j] = g_CB[ch * 16384 + idx];
        Cs[i * 129 + j]  = g_conv[(size_t)(ch * QC + i) * CONVD + HIDC + NS + j];
    }
    for (int idx = tid; idx < 8192; idx += 256) {
        int p = idx >> 7, n = idx & 127;
        SpT[n * 64 + p] = g_states[((size_t)ch * NHh + h) * (PD * NS) + idx];
        xss[idx] = g_conv[(size_t)(ch * QC + (idx >> 6)) * CONVD + h * PD + (idx & 63)];
    }
    if (tid < 128) {
        int r = (ch * QC + tid) * NHh + h;
        cum_s[tid] = g_cum[r];
        dt_s[tid]  = g_dt[r];
    }
    __syncthreads();

    const int i = tid >> 1, ph = tid & 1;
    float4 aD[8], aO[8];
    #pragma unroll
    for (int u = 0; u < 8; u++) { aD[u] = make_float4(0.f,0.f,0.f,0.f); aO[u] = make_float4(0.f,0.f,0.f,0.f); }
    const float ci = cum_s[i];

    // intra-chunk (lower-triangular) attention
    for (int j = 0; j <= i; j++) {
        float m = CBs[i * 129 + j] * __expf(ci - cum_s[j]) * dt_s[j];
        const float4* xr = (const float4*)&xss[j * 64 + ph * 32];
        #pragma unroll
        for (int u = 0; u < 8; u++) fma4(aD[u], m, xr[u]);
    }
    // carried-state contribution
    #pragma unroll 4
    for (int n = 0; n < NS; n++) {
        float cv = Cs[i * 129 + n];
        const float4* sr = (const float4*)&SpT[n * 64 + ph * 32];
        #pragma unroll
        for (int u = 0; u < 8; u++) fma4(aO[u], cv, sr[u]);
    }
    const float ei = __expf(ci);
    const float Dh = Dvec[h];
    const float* xi = &xss[i * 64 + ph * 32];
    float* yo = &g_y[(size_t)(ch * QC + i) * HIDC + h * PD + ph * 32];
    #pragma unroll
    for (int u = 0; u < 8; u++) {
        float4 d = aD[u], o = aO[u];
        float4 r;
        r.x = d.x + ei * o.x + Dh * xi[u * 4 + 0];
        r.y = d.y + ei * o.y + Dh * xi[u * 4 + 1];
        r.z = d.z + ei * o.z + Dh * xi[u * 4 + 2];
        r.w = d.w + ei * o.w + Dh * xi[u * 4 + 3];
        *reinterpret_cast<float4*>(&yo[u * 4]) = r;
    }
}

// ---------------- gate with silu(z) + RMSNorm (in-place on g_y) ----------------
__global__ void __launch_bounds__(256) gating_kernel(const float* __restrict__ norm_w) {
    __shared__ float red[256];
    const int bl = blockIdx.x, tid = threadIdx.x;
    float vals[16];
    float ss = 0.f;
    #pragma unroll
    for (int it = 0; it < 16; it++) {
        int idx = it * 256 + tid;
        float yv = g_y[(size_t)bl * HIDC + idx];
        float z  = g_zx[(size_t)bl * DINn + idx];
        float yz = yv * (z / (1.f + expf(-z)));
        vals[it] = yz;
        ss += yz * yz;
    }
    red[tid] = ss;
    __syncthreads();
    for (int s = 128; s > 0; s >>= 1) {
        if (tid < s) red[tid] += red[tid + s];
        __syncthreads();
    }
    float sc = rsqrtf(red[0] / (float)HIDC + 1e-5f);
    #pragma unroll
    for (int it = 0; it < 16; it++) {
        int idx = it * 256 + tid;
        g_y[(size_t)bl * HIDC + idx] = vals[it] * sc * norm_w[idx];
    }
}

// ---------------- launch ----------------
extern "C" void kernel_launch(void* const* d_in, const int* in_sizes, int n_in,
                              void* d_out, int out_size) {
    const float* x       = (const float*)d_in[0];
    const float* W_in    = (const float*)d_in[1];
    const float* conv_w  = (const float*)d_in[2];
    const float* dt_bias = (const float*)d_in[3];
    const float* A_log   = (const float*)d_in[4];
    const float* Dv      = (const float*)d_in[5];
    const float* norm_w  = (const float*)d_in[6];
    const float* W_out   = (const float*)d_in[7];
    float* out = (float*)d_out;

    float *zx_p, *y_p;
    cudaGetSymbolAddress((void**)&zx_p, g_zx);
    cudaGetSymbolAddress((void**)&y_p, g_y);

    cudaFuncSetAttribute(gemm_tc_kernel, cudaFuncAttributeMaxDynamicSharedMemorySize, GTC_SMEM);
    cudaFuncSetAttribute(cb_kernel, cudaFuncAttributeMaxDynamicSharedMemorySize, 132096);
    cudaFuncSetAttribute(ydyoff_kernel, cudaFuncAttributeMaxDynamicSharedMemorySize, 198656);

    // 1) in-proj GEMM: (8192 x 2048) * (8512 x 2048)^T  [fp16 mma.sync]
    gemm_tc_kernel<<<dim3(67, 32), 256, GTC_SMEM>>>(x, W_in, zx_p, BLn, DINn, DIMI);
    // 2) causal conv + silu
    conv_silu_kernel<<<(BLn * CONVD) / 256, 256>>>(conv_w);
    // 3) dt softplus
    dt_kernel<<<(BLn * NHh) / 256, 256>>>(dt_bias);
    // 4) per-chunk cumsum of dt*A
    cum_kernel<<<16, 256>>>(A_log);
    // 5) per-chunk CB gram
    cb_kernel<<<NCT, 256, 132096>>>();
    // 6) chunk states
    states_kernel<<<dim3(NHh, NCT), 256>>>();
    // 7) inter-chunk scan -> Sprev
    scan_kernel<<<dim3(NHh, 2), 256>>>();
    // 8) Yd + Yoff + D*xs
    ydyoff_kernel<<<dim3(NHh, NCT), 256, 198656>>>(Dv);
    // 9) gate + rmsnorm
    gating_kernel<<<BLn, 256>>>(norm_w);
    // 10) out-proj GEMM: (8192 x 4096) * (2048 x 4096)^T  [fp16 mma.sync]
    gemm_tc_kernel<<<dim3(16, 32), 256, GTC_SMEM>>>(y_p, W_out, out, BLn, DIMI, HIDC);
}

// round 7
// speedup vs baseline: 1.9552x; 1.0272x over previous
#include <cuda_runtime.h>
#include <cuda_fp16.h>
#include <cstdint>

// ---------------- problem constants ----------------
#define BLn    8192      // B * L
#define LSEQ   4096
#define DIMI   2048
#define DINn   8512      // 2*HID + 2*G*N + H
#define HIDC   4096
#define CONVD  4352      // HID + 2*G*N
#define NHh    64        // heads
#define PD     64        // head dim
#define NS     128       // state dim
#define QC     128       // chunk len
#define NCT    64        // total chunks = B * (L/Q)

// ---------------- scratch (device globals; allocation-free rule) ----------------
__device__ float g_zx[(size_t)BLn * DINn];        // in-proj output (z | xBC | dt_raw)
__device__ float g_conv[(size_t)BLn * CONVD];     // conv+silu output (xs | B | C)
__device__ float g_dt[BLn * NHh];                 // softplus(dt_raw + bias)
__device__ float g_cum[BLn * NHh];                // per-chunk cumsum of dt*A
__device__ float g_CB[NCT * QC * QC];             // per-chunk C.B^T gram
__device__ float g_states[(size_t)NCT * NHh * PD * NS];  // chunk states, then Sprev in-place
__device__ float g_y[(size_t)BLn * HIDC];         // y, then yn in-place

__device__ __forceinline__ void fma4(float4& a, float s, const float4 v) {
    a.x += s * v.x; a.y += s * v.y; a.z += s * v.z; a.w += s * v.w;
}

// =======================================================================
//  fp16 mma.sync m16n8k16 GEMM:  C[M=8192 slice, Nvalid] = A * B^T
//  fp32 in/out, fp16 operands, fp32 accum. CTA tile 256xNT, 8 warps (4x2).
// =======================================================================

__device__ __forceinline__ uint32_t pack_h2(float x, float y) {
    uint32_t r;
    asm("cvt.rn.f16x2.f32 %0, %1, %2;" : "=r"(r) : "f"(y), "f"(x));
    return r;
}

__device__ __forceinline__ void mma_f16(float* d, const uint32_t* a, const uint32_t* b) {
    asm volatile(
        "mma.sync.aligned.m16n8k16.row.col.f32.f16.f16.f32 "
        "{%0,%1,%2,%3}, {%4,%5,%6,%7}, {%8,%9}, {%0,%1,%2,%3};"
        : "+f"(d[0]), "+f"(d[1]), "+f"(d[2]), "+f"(d[3])
        : "r"(a[0]), "r"(a[1]), "r"(a[2]), "r"(a[3]), "r"(b[0]), "r"(b[1]));
}

#define AH 20                                 // half stride per smem row (16 + pad 4)

template<int NT>
__global__ void __launch_bounds__(256) gemm_tc(
    const float* __restrict__ A, const float* __restrict__ B, float* __restrict__ C,
    int Nvalid, int K, int ldC)
{
    constexpr int NFRAG = NT / 16;            // n8-frags per warp
    constexpr int NB    = NT / 64;            // B staging v-iters
    constexpr int SSTH  = (256 + NT) * AH;    // halves per stage
    extern __shared__ __half hsm[];
    const int tid  = threadIdx.x;
    const int wid  = tid >> 5, lane = tid & 31;
    const int gID  = lane >> 2, tig = lane & 3;
    const int wM   = (wid >> 1) * 64;
    const int wN   = (wid & 1) * (NT / 2);
    const int cRow = blockIdx.y * 256;
    const int cCol = blockIdx.x * NT;
    const int KT   = K >> 4;

    const int srow = tid >> 2;
    const int sc4  = (tid & 3) * 4;
    bool bok[NB];
    #pragma unroll
    for (int v = 0; v < NB; v++) bok[v] = (cCol + v * 64 + srow) < Nvalid;

    float acc[4][NFRAG][4];
    #pragma unroll
    for (int mi = 0; mi < 4; mi++)
        #pragma unroll
        for (int ni = 0; ni < NFRAG; ni++)
            #pragma unroll
            for (int u = 0; u < 4; u++) acc[mi][ni][u] = 0.f;

    auto store_stage = [&](int slot, const float4* ra, const float4* rb) {
        __half* As = hsm + slot * SSTH;
        __half* Bs = As + 256 * AH;
        #pragma unroll
        for (int v = 0; v < 4; v++) {
            uint2 pk = make_uint2(pack_h2(ra[v].x, ra[v].y), pack_h2(ra[v].z, ra[v].w));
            *reinterpret_cast<uint2*>(&As[(v * 64 + srow) * AH + sc4]) = pk;
        }
        #pragma unroll
        for (int v = 0; v < NB; v++) {
            uint2 pk = make_uint2(pack_h2(rb[v].x, rb[v].y), pack_h2(rb[v].z, rb[v].w));
            *reinterpret_cast<uint2*>(&Bs[(v * 64 + srow) * AH + sc4]) = pk;
        }
    };

    float4 ra[4], rb[NB];
    // prologue: tile 0
    {
        #pragma unroll
        for (int v = 0; v < 4; v++)
            ra[v] = *reinterpret_cast<const float4*>(A + (size_t)(cRow + v * 64 + srow) * K + sc4);
        #pragma unroll
        for (int v = 0; v < NB; v++)
            rb[v] = bok[v] ? *reinterpret_cast<const float4*>(B + (size_t)(cCol + v * 64 + srow) * K + sc4)
                           : make_float4(0.f, 0.f, 0.f, 0.f);
        store_stage(0, ra, rb);
    }
    __syncthreads();

    for (int kt = 0; kt < KT; kt++) {
        const int b = kt & 1;
        const bool more = (kt + 1 < KT);
        if (more) {
            const int kb = (kt + 1) << 4;
            #pragma unroll
            for (int v = 0; v < 4; v++)
                ra[v] = *reinterpret_cast<const float4*>(A + (size_t)(cRow + v * 64 + srow) * K + kb + sc4);
            #pragma unroll
            for (int v = 0; v < NB; v++)
                rb[v] = bok[v] ? *reinterpret_cast<const float4*>(B + (size_t)(cCol + v * 64 + srow) * K + kb + sc4)
                               : make_float4(0.f, 0.f, 0.f, 0.f);
        }

        const __half* As = hsm + b * SSTH;
        const __half* Bs = As + 256 * AH;
        const int k0 = tig * 2;
        uint32_t af[4][4], bf[NFRAG][2];
        #pragma unroll
        for (int mi = 0; mi < 4; mi++) {
            const int r = wM + mi * 16 + gID;
            af[mi][0] = *reinterpret_cast<const uint32_t*>(&As[r * AH + k0]);
            af[mi][1] = *reinterpret_cast<const uint32_t*>(&As[(r + 8) * AH + k0]);
            af[mi][2] = *reinterpret_cast<const uint32_t*>(&As[r * AH + k0 + 8]);
            af[mi][3] = *reinterpret_cast<const uint32_t*>(&As[(r + 8) * AH + k0 + 8]);
        }
        #pragma unroll
        for (int ni = 0; ni < NFRAG; ni++) {
            const int r = wN + ni * 8 + gID;
            bf[ni][0] = *reinterpret_cast<const uint32_t*>(&Bs[r * AH + k0]);
            bf[ni][1] = *reinterpret_cast<const uint32_t*>(&Bs[r * AH + k0 + 8]);
        }
        #pragma unroll
        for (int mi = 0; mi < 4; mi++)
            #pragma unroll
            for (int ni = 0; ni < NFRAG; ni++)
                mma_f16(acc[mi][ni], af[mi], bf[ni]);

        if (more) store_stage(b ^ 1, ra, rb);
        __syncthreads();
    }

    // epilogue
    #pragma unroll
    for (int mi = 0; mi < 4; mi++) {
        const int r0 = cRow + wM + mi * 16 + gID;
        #pragma unroll
        for (int ni = 0; ni < NFRAG; ni++) {
            const int c = cCol + wN + ni * 8 + tig * 2;
            if (c < Nvalid) {
                *reinterpret_cast<float2*>(C + (size_t)r0 * ldC + c) =
                    make_float2(acc[mi][ni][0], acc[mi][ni][1]);
                *reinterpret_cast<float2*>(C + (size_t)(r0 + 8) * ldC + c) =
                    make_float2(acc[mi][ni][2], acc[mi][ni][3]);
            }
        }
    }
}

#define SMEM_NT128 (2 * (256 + 128) * AH * 2)   // 30720 B
#define SMEM_NT64  (2 * (256 + 64) * AH * 2)    // 25600 B

// ---------------- causal depthwise conv (K=4) + SiLU ----------------
__global__ void __launch_bounds__(256) conv_silu_kernel(const float* __restrict__ w) {
    size_t idx = (size_t)blockIdx.x * 256 + threadIdx.x;   // over BL*CONVD
    int c = (int)(idx % CONVD);
    int bl = (int)(idx / CONVD);
    int l = bl & (LSEQ - 1);
    float acc = 0.f;
    #pragma unroll
    for (int k = 0; k < 4; k++) {
        int lo = l - 3 + k;
        if (lo >= 0)
            acc += g_zx[(size_t)(bl - 3 + k) * DINn + HIDC + c] * w[c * 4 + k];
    }
    float s = 1.f / (1.f + expf(-acc));
    g_conv[(size_t)bl * CONVD + c] = acc * s;
}

// ---------------- dt = softplus(dt_raw + bias) ----------------
__global__ void __launch_bounds__(256) dt_kernel(const float* __restrict__ dt_bias) {
    int idx = blockIdx.x * 256 + threadIdx.x;    // over BL*NH
    int h = idx & 63;
    int bl = idx >> 6;
    float v = g_zx[(size_t)bl * DINn + (HIDC + CONVD) + h] + dt_bias[h];
    float d = (v > 20.f) ? v : log1pf(expf(v));
    g_dt[idx] = d;
}

// ---------------- per-chunk cumsum of dt*A (one thread per (ch,h)) ----------------
__global__ void __launch_bounds__(256) cum_kernel(const float* __restrict__ A_log) {
    int idx = blockIdx.x * 256 + threadIdx.x;   // 0..4095
    int h = idx & 63, ch = idx >> 6;
    float A = -expf(A_log[h]);
    float run = 0.f;
    for (int q = 0; q < QC; q++) {
        int r = (ch * QC + q) * NHh + h;
        run += g_dt[r] * A;
        g_cum[r] = run;
    }
}

// ---------------- per-chunk CB[i][j] = sum_n C[i,n]*B[j,n] ----------------
__global__ void __launch_bounds__(256) cb_kernel() {
    extern __shared__ float sh[];
    float* Bsh = sh;             // 128 x 129
    float* Csh = sh + 16512;     // 128 x 129
    int ch = blockIdx.x;
    int tid = threadIdx.x;
    for (int idx = tid; idx < 16384; idx += 256) {
        int i = idx >> 7, n = idx & 127;
        size_t row = (size_t)(ch * QC + i) * CONVD;
        Bsh[i * 129 + n] = g_conv[row + HIDC + n];
        Csh[i * 129 + n] = g_conv[row + HIDC + NS + n];
    }
    __syncthreads();
    int tx = tid & 15, ty = tid >> 4;
    float acc[8][8];
    #pragma unroll
    for (int i = 0; i < 8; i++)
        #pragma unroll
        for (int j = 0; j < 8; j++) acc[i][j] = 0.f;
    for (int n = 0; n < NS; n++) {
        float a[8], b[8];
        #pragma unroll
        for (int u = 0; u < 8; u++) a[u] = Csh[(ty * 8 + u) * 129 + n];
        #pragma unroll
        for (int u = 0; u < 8; u++) b[u] = Bsh[(tx * 8 + u) * 129 + n];
        #pragma unroll
        for (int i = 0; i < 8; i++)
            #pragma unroll
            for (int j = 0; j < 8; j++) acc[i][j] += a[i] * b[j];
    }
    #pragma unroll
    for (int i = 0; i < 8; i++)
        #pragma unroll
        for (int j0 = 0; j0 < 8; j0 += 4)
            *reinterpret_cast<float4*>(&g_CB[ch * 16384 + (ty * 8 + i) * 128 + tx * 8 + j0]) =
                make_float4(acc[i][j0], acc[i][j0 + 1], acc[i][j0 + 2], acc[i][j0 + 3]);
}

// ---------------- chunk states: states[h,p,n] = sum_q wdec[q]*xs[q,p]*B[q,n] ----------------
__global__ void __launch_bounds__(256) states_kernel() {
    __shared__ float Bs[32 * 128];
    __shared__ float xss[32 * 64];
    __shared__ float wdec[128];
    __shared__ float cl;
    const int h = blockIdx.x, ch = blockIdx.y;
    const int tid = threadIdx.x;
    if (tid == 0) cl = g_cum[(ch * QC + QC - 1) * NHh + h];
    __syncthreads();
    if (tid < 128) {
        int r = (ch * QC + tid) * NHh + h;
        wdec[tid] = __expf(cl - g_cum[r]) * g_dt[r];
    }
    const int p = tid >> 2, ng = tid & 3;
    float4 acc4[8];
    #pragma unroll
    for (int u = 0; u < 8; u++) acc4[u] = make_float4(0.f, 0.f, 0.f, 0.f);

    for (int qt = 0; qt < 4; qt++) {
        __syncthreads();
        for (int idx = tid; idx < 4096; idx += 256) {
            int qq = idx >> 7, n = idx & 127;
            Bs[idx] = g_conv[(size_t)(ch * QC + qt * 32 + qq) * CONVD + HIDC + n];
        }
        for (int idx = tid; idx < 2048; idx += 256) {
            int qq = idx >> 6, pp = idx & 63;
            xss[idx] = g_conv[(size_t)(ch * QC + qt * 32 + qq) * CONVD + h * PD + pp];
        }
        __syncthreads();
        #pragma unroll 4
        for (int qq = 0; qq < 32; qq++) {
            float coef = wdec[qt * 32 + qq] * xss[qq * 64 + p];
            const float4* bp = (const float4*)&Bs[qq * 128 + ng * 32];
            #pragma unroll
            for (int u = 0; u < 8; u++) fma4(acc4[u], coef, bp[u]);
        }
    }
    size_t base = ((size_t)ch * NHh + h) * (PD * NS) + (size_t)p * NS + ng * 32;
    #pragma unroll
    for (int u = 0; u < 8; u++)
        *reinterpret_cast<float4*>(&g_states[base + u * 4]) = acc4[u];
}

// ---------------- sequential inter-chunk scan (in-place: states -> Sprev) ----------------
__global__ void __launch_bounds__(256) scan_kernel() {
    const int h = blockIdx.x, b = blockIdx.y;
    const int t = threadIdx.x;
    float S[32];
    #pragma unroll
    for (int i = 0; i < 32; i++) S[i] = 0.f;
    for (int c = 0; c < 32; c++) {
        int ch = b * 32 + c;
        float dec = __expf(g_cum[(ch * QC + QC - 1) * NHh + h]);
        size_t base = ((size_t)ch * NHh + h) * (PD * NS);
        #pragma unroll
        for (int i = 0; i < 32; i++) {
            size_t id = base + (size_t)i * 256 + t;
            float st = g_states[id];
            g_states[id] = S[i];               // Sprev (state before this chunk)
            S[i] = S[i] * dec + st;
        }
    }
}

// ---------------- Yd + Yoff + D*xs -> y ----------------
__global__ void __launch_bounds__(256) ydyoff_kernel(const float* __restrict__ Dvec) {
    extern __shared__ float sh[];
    float* CBs   = sh;                 // 128 x 129
    float* Cs    = sh + 16512;         // 128 x 129
    float* SpT   = sh + 33024;         // [n][p] 128 x 64
    float* xss   = sh + 41216;         // [j][p] 128 x 64
    float* cum_s = sh + 49408;         // 128
    float* dt_s  = sh + 49536;         // 128
    const int h = blockIdx.x, ch = blockIdx.y, tid = threadIdx.x;

    for (int idx = tid; idx < 16384; idx += 256) {
        int i = idx >> 7, j = idx & 127;
        CBs[i * 129 + j] = g_CB[ch * 16384 + idx];
        Cs[i * 129 + j]  = g_conv[(size_t)(ch * QC + i) * CONVD + HIDC + NS + j];
    }
    for (int idx = tid; idx < 8192; idx += 256) {
        int p = idx >> 7, n = idx & 127;
        SpT[n * 64 + p] = g_states[((size_t)ch * NHh + h) * (PD * NS) + idx];
        xss[idx] = g_conv[(size_t)(ch * QC + (idx >> 6)) * CONVD + h * PD + (idx & 63)];
    }
    if (tid < 128) {
        int r = (ch * QC + tid) * NHh + h;
        cum_s[tid] = g_cum[r];
        dt_s[tid]  = g_dt[r];
    }
    __syncthreads();

    const int i = tid >> 1, ph = tid & 1;
    float4 aD[8], aO[8];
    #pragma unroll
    for (int u = 0; u < 8; u++) { aD[u] = make_float4(0.f,0.f,0.f,0.f); aO[u] = make_float4(0.f,0.f,0.f,0.f); }
    const float ci = cum_s[i];

    // intra-chunk (lower-triangular) attention
    for (int j = 0; j <= i; j++) {
        float m = CBs[i * 129 + j] * __expf(ci - cum_s[j]) * dt_s[j];
        const float4* xr = (const float4*)&xss[j * 64 + ph * 32];
        #pragma unroll
        for (int u = 0; u < 8; u++) fma4(aD[u], m, xr[u]);
    }
    // carried-state contribution
    #pragma unroll 4
    for (int n = 0; n < NS; n++) {
        float cv = Cs[i * 129 + n];
        const float4* sr = (const float4*)&SpT[n * 64 + ph * 32];
        #pragma unroll
        for (int u = 0; u < 8; u++) fma4(aO[u], cv, sr[u]);
    }
    const float ei = __expf(ci);
    const float Dh = Dvec[h];
    const float* xi = &xss[i * 64 + ph * 32];
    float* yo = &g_y[(size_t)(ch * QC + i) * HIDC + h * PD + ph * 32];
    #pragma unroll
    for (int u = 0; u < 8; u++) {
        float4 d = aD[u], o = aO[u];
        float4 r;
        r.x = d.x + ei * o.x + Dh * xi[u * 4 + 0];
        r.y = d.y + ei * o.y + Dh * xi[u * 4 + 1];
        r.z = d.z + ei * o.z + Dh * xi[u * 4 + 2];
        r.w = d.w + ei * o.w + Dh * xi[u * 4 + 3];
        *reinterpret_cast<float4*>(&yo[u * 4]) = r;
    }
}

// ---------------- gate with silu(z) + RMSNorm (in-place on g_y) ----------------
__global__ void __launch_bounds__(256) gating_kernel(const float* __restrict__ norm_w) {
    __shared__ float red[256];
    const int bl = blockIdx.x, tid = threadIdx.x;
    float vals[16];
    float ss = 0.f;
    #pragma unroll
    for (int it = 0; it < 16; it++) {
        int idx = it * 256 + tid;
        float yv = g_y[(size_t)bl * HIDC + idx];
        float z  = g_zx[(size_t)bl * DINn + idx];
        float yz = yv * (z / (1.f + expf(-z)));
        vals[it] = yz;
        ss += yz * yz;
    }
    red[tid] = ss;
    __syncthreads();
    for (int s = 128; s > 0; s >>= 1) {
        if (tid < s) red[tid] += red[tid + s];
        __syncthreads();
    }
    float sc = rsqrtf(red[0] / (float)HIDC + 1e-5f);
    #pragma unroll
    for (int it = 0; it < 16; it++) {
        int idx = it * 256 + tid;
        g_y[(size_t)bl * HIDC + idx] = vals[it] * sc * norm_w[idx];
    }
}

// ---------------- launch ----------------
extern "C" void kernel_launch(void* const* d_in, const int* in_sizes, int n_in,
                              void* d_out, int out_size) {
    const float* x       = (const float*)d_in[0];
    const float* W_in    = (const float*)d_in[1];
    const float* conv_w  = (const float*)d_in[2];
    const float* dt_bias = (const float*)d_in[3];
    const float* A_log   = (const float*)d_in[4];
    const float* Dv      = (const float*)d_in[5];
    const float* norm_w  = (const float*)d_in[6];
    const float* W_out   = (const float*)d_in[7];
    float* out = (float*)d_out;

    float *zx_p, *y_p;
    cudaGetSymbolAddress((void**)&zx_p, g_zx);
    cudaGetSymbolAddress((void**)&y_p, g_y);

    // one-time side stream + events (created on the uncaptured correctness call)
    static cudaStream_t s2 = nullptr;
    static cudaEvent_t evA = nullptr, evB = nullptr;
    if (s2 == nullptr) {
        cudaStreamCreateWithFlags(&s2, cudaStreamNonBlocking);
        cudaEventCreateWithFlags(&evA, cudaEventDisableTiming);
        cudaEventCreateWithFlags(&evB, cudaEventDisableTiming);
        cudaFuncSetAttribute(gemm_tc<128>, cudaFuncAttributeMaxDynamicSharedMemorySize, SMEM_NT128);
        cudaFuncSetAttribute(gemm_tc<64>,  cudaFuncAttributeMaxDynamicSharedMemorySize, SMEM_NT64);
        cudaFuncSetAttribute(cb_kernel, cudaFuncAttributeMaxDynamicSharedMemorySize, 132096);
        cudaFuncSetAttribute(ydyoff_kernel, cudaFuncAttributeMaxDynamicSharedMemorySize, 198656);
    }

    // 1a) in-proj GEMM, xBC+dt columns [4096, 8512): needed by the mid-chain
    gemm_tc<128><<<dim3(35, 32), 256, SMEM_NT128>>>(
        x, W_in + (size_t)HIDC * DIMI, zx_p + HIDC, DINn - HIDC, DIMI, DINn);
    cudaEventRecord(evA, 0);

    // 1b) in-proj GEMM, z columns [0, 4096) — on side stream, overlapped with mid-chain
    cudaStreamWaitEvent(s2, evA, 0);
    gemm_tc<128><<<dim3(32, 32), 256, SMEM_NT128, s2>>>(
        x, W_in, zx_p, HIDC, DIMI, DINn);
    cudaEventRecord(evB, s2);

    // mid-chain on default stream (concurrent with 1b)
    conv_silu_kernel<<<(BLn * CONVD) / 256, 256>>>(conv_w);
    dt_kernel<<<(BLn * NHh) / 256, 256>>>(dt_bias);
    cum_kernel<<<16, 256>>>(A_log);
    cb_kernel<<<NCT, 256, 132096>>>();
    states_kernel<<<dim3(NHh, NCT), 256>>>();
    scan_kernel<<<dim3(NHh, 2), 256>>>();
    ydyoff_kernel<<<dim3(NHh, NCT), 256, 198656>>>(Dv);

    // join: gating needs z columns from 1b
    cudaStreamWaitEvent(0, evB, 0);
    gating_kernel<<<BLn, 256>>>(norm_w);

    // 2) out-proj GEMM: (8192 x 4096) * (2048 x 4096)^T — NT=64 for wave balance
    gemm_tc<64><<<dim3(32, 32), 256, SMEM_NT64>>>(y_p, W_out, out, DIMI, HIDC, DIMI);
}